// round 2
// baseline (speedup 1.0000x reference)
#include <cuda_runtime.h>

#define NN   10000
#define OO   16
#define CC   64
#define EE   100000
#define KDD  64
#define NOC  (NN*OO*CC)          // 10,240,000
#define TILE (OO*CC)             // 1024 floats = 4KB per node/edge tile

// -------- device scratch (no allocations allowed) --------
__device__ __align__(16) float g_x1[NOC];           // 41 MB spatial-conv accumulator
__device__ __align__(16) float g_fk[OO*OO*CC];      // fiber kernel (pre-divided by O)

// =========================================================
// K0: zero the x1 accumulator
// =========================================================
__global__ void k_zero() {
    float4* p = reinterpret_cast<float4*>(g_x1);
    const int n4 = NOC / 4;
    int i = blockIdx.x * blockDim.x + threadIdx.x;
    const int stride = gridDim.x * blockDim.x;
    const float4 z = make_float4(0.f, 0.f, 0.f, 0.f);
    for (; i < n4; i += stride) p[i] = z;
}

// =========================================================
// K1: fk[p][o][c] = (1/O) * sum_kd FKB[p,o,kd] * FW[kd,c]
// grid = 256 (p*16+o), block = 64 (c)
// =========================================================
__global__ void k_fk(const float* __restrict__ fkb, const float* __restrict__ fw) {
    __shared__ float s[KDD];
    const int po = blockIdx.x;
    const int c  = threadIdx.x;
    s[c] = fkb[po * KDD + c];
    __syncthreads();
    float acc = 0.f;
#pragma unroll 16
    for (int kd = 0; kd < KDD; kd++)
        acc += s[kd] * fw[kd * CC + c];
    g_fk[po * CC + c] = acc * (1.0f / (float)OO);
}

// =========================================================
// K2: edge conv. Per edge e:
//   k[o][c] = sum_kd KB[e,o,kd] * W[kd,c]
//   msg     = x[src] * k
//   x1[dst] += msg   (via cp.reduce.async.bulk, 4KB per edge)
// block = 256 threads, 8 edges / block, grid = E/8 = 12500
// Thread layout: c = tid&63 (W column in registers), 4 o-rows per thread.
// =========================================================
__global__ void __launch_bounds__(256) k_edge(
    const float* __restrict__ x,
    const float* __restrict__ kb,
    const int*   __restrict__ ei,
    const float* __restrict__ kw)
{
    __shared__ __align__(16) float KBs[TILE];      // current edge's kernel basis
    __shared__ __align__(16) float MSG[2][TILE];   // double-buffered message tile

    const int tid  = threadIdx.x;
    const int c    = tid & 63;
    const int orow = tid >> 6;   // 0..3, warp-uniform

    // W column lives in registers, reused across all 8 edges
    float Wr[KDD];
#pragma unroll
    for (int kd = 0; kd < KDD; kd++)
        Wr[kd] = kw[kd * CC + c];

    const long long ebase = (long long)blockIdx.x * 8;

#pragma unroll 1
    for (int it = 0; it < 8; ++it) {
        const long long e = ebase + it;
        const int src = ei[e];
        const int dst = ei[EE + e];

        __syncthreads();  // all reads of KBs from previous iter complete
        ((float4*)KBs)[tid] = ((const float4*)(kb + e * (long long)TILE))[tid];

        // prefetch x[src] rows this thread needs (L2-resident, coalesced)
        float xv[4];
#pragma unroll
        for (int i = 0; i < 4; i++)
            xv[i] = x[(long long)src * TILE + (orow * 4 + i) * CC + c];

        __syncthreads();  // KBs ready

        float acc[4] = {0.f, 0.f, 0.f, 0.f};
#pragma unroll
        for (int kd4 = 0; kd4 < 16; kd4++) {
#pragma unroll
            for (int i = 0; i < 4; i++) {
                const float4 kv = ((const float4*)KBs)[(orow * 4 + i) * 16 + kd4];
                acc[i] += kv.x * Wr[kd4 * 4 + 0];
                acc[i] += kv.y * Wr[kd4 * 4 + 1];
                acc[i] += kv.z * Wr[kd4 * 4 + 2];
                acc[i] += kv.w * Wr[kd4 * 4 + 3];
            }
        }

        const int buf = it & 1;
        // make sure the bulk-reduce issued 2 iterations ago (same buffer) drained
        if (tid == 0 && it >= 2)
            asm volatile("cp.async.bulk.wait_group 1;" ::: "memory");
        __syncthreads();

#pragma unroll
        for (int i = 0; i < 4; i++)
            MSG[buf][(orow * 4 + i) * CC + c] = xv[i] * acc[i];
        __syncthreads();

        if (tid == 0) {
            asm volatile("fence.proxy.async.shared::cta;" ::: "memory");
            unsigned saddr = (unsigned)__cvta_generic_to_shared(&MSG[buf][0]);
            float* gptr = g_x1 + (long long)dst * TILE;
            asm volatile(
                "cp.reduce.async.bulk.global.shared::cta.bulk_group.add.f32 [%0], [%1], %2;"
                :: "l"(gptr), "r"(saddr), "r"(4096) : "memory");
            asm volatile("cp.async.bulk.commit_group;" ::: "memory");
        }
    }
    if (tid == 0)
        asm volatile("cp.async.bulk.wait_group 0;" ::: "memory");
}

// =========================================================
// K3: fused fiber conv + bias + LayerNorm + MLP + layer-scale + residual
// block = 256 threads, 64 nodes / block, grid = ceil(N/64) = 157
// smem: w1(64KB) + w2(64KB) + fk(64KB) + tiles (~26KB) = 218.25 KB
// =========================================================
#define SMEM_FLOATS (16384*3 + 1024 + 1024 + 4096 + 64*5 + 256)

__global__ void __launch_bounds__(256) k_fuse(
    const float* __restrict__ x,
    const float* __restrict__ cb,
    const float* __restrict__ lns,
    const float* __restrict__ lnb,
    const float* __restrict__ w1,
    const float* __restrict__ b1,
    const float* __restrict__ w2,
    const float* __restrict__ b2,
    const float* __restrict__ ls,
    float*       __restrict__ out)
{
    extern __shared__ __align__(16) float sm[];
    float* w1_s  = sm;               // [c][j] 64x256
    float* w2_s  = w1_s + 16384;     // [j][c] 256x64
    float* fk_s  = w2_s + 16384;     // [p][o][c]
    float* x2_s  = fk_s + 16384;     // [p][c] 16x64
    float* h_s   = x2_s + 1024;      // [c][p] 64x16 (LN output, transposed)
    float* h1_s  = h_s  + 1024;      // [j][p] 256x16
    float* cb_s  = h1_s + 4096;
    float* lns_s = cb_s + 64;
    float* lnb_s = lns_s + 64;
    float* b2_s  = lnb_s + 64;
    float* ls_s  = b2_s + 64;
    float* b1_s  = ls_s + 64;        // 256

    const int tid = threadIdx.x;
    for (int i = tid; i < 16384; i += 256) {
        w1_s[i] = w1[i];
        w2_s[i] = w2[i];
        fk_s[i] = g_fk[i];
    }
    if (tid < 64) {
        cb_s[tid]  = cb[tid];
        lns_s[tid] = lns[tid];
        lnb_s[tid] = lnb[tid];
        b2_s[tid]  = b2[tid];
        ls_s[tid]  = ls[tid] * 1e-6f;   // fold LS_VAL
    }
    b1_s[tid] = b1[tid];
    __syncthreads();

    const int c    = tid & 63;
    const int pg   = tid >> 6;       // 0..3
    const int wrp  = tid >> 5;       // 0..7
    const int lane = tid & 31;

    const int b0   = blockIdx.x * 64;
    const int bend = min(b0 + 64, NN);

    for (int b = b0; b < bend; ++b) {
        const long long base = (long long)b * TILE;

        // ---- fiber conv: x2[p][c] = sum_o x1[b,o,c] * fk[p,o,c] + conv_bias ----
        const float* x1p = g_x1 + base;
        float x1r[16];
#pragma unroll
        for (int o = 0; o < 16; o++)
            x1r[o] = x1p[o * 64 + c];
#pragma unroll
        for (int i = 0; i < 4; i++) {
            const int p = pg * 4 + i;
            float a = cb_s[c];
#pragma unroll
            for (int o = 0; o < 16; o++)
                a += x1r[o] * fk_s[p * 1024 + o * 64 + c];
            x2_s[p * 64 + c] = a;
        }
        __syncthreads();

        // ---- LayerNorm over c: warp wrp handles rows 2*wrp, 2*wrp+1 ----
#pragma unroll
        for (int rr = 0; rr < 2; ++rr) {
            const int r = 2 * wrp + rr;
            const float v0 = x2_s[r * 64 + lane];
            const float v1 = x2_s[r * 64 + lane + 32];
            float s = v0 + v1;
            float q = v0 * v0 + v1 * v1;
#pragma unroll
            for (int off = 16; off; off >>= 1) {
                s += __shfl_xor_sync(0xffffffffu, s, off);
                q += __shfl_xor_sync(0xffffffffu, q, off);
            }
            const float mu  = s * (1.0f / 64.0f);
            const float var = q * (1.0f / 64.0f) - mu * mu;
            const float rs  = rsqrtf(var + 1e-6f);
            h_s[lane * 16 + r]        = (v0 - mu) * rs * lns_s[lane]      + lnb_s[lane];
            h_s[(lane + 32) * 16 + r] = (v1 - mu) * rs * lns_s[lane + 32] + lnb_s[lane + 32];
        }
        __syncthreads();

        // ---- MLP layer 1: h1[p][j] = relu(sum_c h[p][c]*w1[c][j] + b1[j]), j = tid ----
        {
            float a[16];
            const float bb = b1_s[tid];
#pragma unroll
            for (int p = 0; p < 16; p++) a[p] = bb;
#pragma unroll 8
            for (int cc = 0; cc < 64; ++cc) {
                const float wv = w1_s[cc * 256 + tid];
                const float4 ha = *(const float4*)(h_s + cc * 16 + 0);
                const float4 hb = *(const float4*)(h_s + cc * 16 + 4);
                const float4 hc = *(const float4*)(h_s + cc * 16 + 8);
                const float4 hd = *(const float4*)(h_s + cc * 16 + 12);
                a[0]  += ha.x * wv; a[1]  += ha.y * wv; a[2]  += ha.z * wv; a[3]  += ha.w * wv;
                a[4]  += hb.x * wv; a[5]  += hb.y * wv; a[6]  += hb.z * wv; a[7]  += hb.w * wv;
                a[8]  += hc.x * wv; a[9]  += hc.y * wv; a[10] += hc.z * wv; a[11] += hc.w * wv;
                a[12] += hd.x * wv; a[13] += hd.y * wv; a[14] += hd.z * wv; a[15] += hd.w * wv;
            }
#pragma unroll
            for (int p = 0; p < 16; p++) a[p] = fmaxf(a[p], 0.0f);
            *(float4*)(h1_s + tid * 16 + 0)  = make_float4(a[0],  a[1],  a[2],  a[3]);
            *(float4*)(h1_s + tid * 16 + 4)  = make_float4(a[4],  a[5],  a[6],  a[7]);
            *(float4*)(h1_s + tid * 16 + 8)  = make_float4(a[8],  a[9],  a[10], a[11]);
            *(float4*)(h1_s + tid * 16 + 12) = make_float4(a[12], a[13], a[14], a[15]);
        }
        __syncthreads();

        // ---- MLP layer 2 + layer scale + residual ----
        {
            float a[4];
            const float bb = b2_s[c];
#pragma unroll
            for (int i = 0; i < 4; i++) a[i] = bb;
            const int p0 = pg * 4;
#pragma unroll 8
            for (int j = 0; j < 256; ++j) {
                const float wv = w2_s[j * 64 + c];
                const float4 hv = *(const float4*)(h1_s + j * 16 + p0);
                a[0] += hv.x * wv;
                a[1] += hv.y * wv;
                a[2] += hv.z * wv;
                a[3] += hv.w * wv;
            }
            const float g = ls_s[c];
#pragma unroll
            for (int i = 0; i < 4; i++) {
                const int p = p0 + i;
                out[base + p * 64 + c] = g * a[i] + x[base + p * 64 + c];
            }
        }
        __syncthreads();  // protect x2_s/h_s/h1_s for next node
    }
}

// =========================================================
extern "C" void kernel_launch(void* const* d_in, const int* in_sizes, int n_in,
                              void* d_out, int out_size)
{
    (void)in_sizes; (void)n_in; (void)out_size;
    const float* x   = (const float*)d_in[0];
    const float* kb  = (const float*)d_in[1];
    const float* fkb = (const float*)d_in[2];
    const int*   ei  = (const int*)  d_in[3];
    const float* kw  = (const float*)d_in[4];
    const float* fkw = (const float*)d_in[5];
    const float* cb  = (const float*)d_in[6];
    const float* lns = (const float*)d_in[7];
    const float* lnb = (const float*)d_in[8];
    const float* w1  = (const float*)d_in[9];
    const float* b1  = (const float*)d_in[10];
    const float* w2  = (const float*)d_in[11];
    const float* b2  = (const float*)d_in[12];
    const float* ls  = (const float*)d_in[13];
    float* out = (float*)d_out;

    const int smem_bytes = SMEM_FLOATS * 4;   // ~218.4 KB
    cudaFuncSetAttribute(k_fuse, cudaFuncAttributeMaxDynamicSharedMemorySize, smem_bytes);

    k_zero<<<2560, 256>>>();
    k_fk<<<OO * OO, CC>>>(fkb, fkw);
    k_edge<<<EE / 8, 256>>>(x, kb, ei, kw);
    k_fuse<<<(NN + 63) / 64, 256, smem_bytes>>>(x, cb, lns, lnb, w1, b1, w2, b2, ls, out);
}

// round 3
// speedup vs baseline: 4.7236x; 4.7236x over previous
#include <cuda_runtime.h>
#include <cuda_bf16.h>

#define NN   10000
#define OO   16
#define CC   64
#define EE   100000
#define KDD  64
#define NOC  (NN*OO*CC)          // 10,240,000
#define TILE (OO*CC)             // 1024 floats = 4KB per node/edge tile

// -------- device scratch (no allocations allowed) --------
__device__ __align__(16) float          g_x1[NOC];      // 41 MB spatial-conv accumulator
__device__ __align__(16) __nv_bfloat162 g_fkb[8192];    // fiber kernel bf16 (pre /O)
__device__ __align__(16) unsigned       g_kwp[2048];    // kernel_w  B-frags (4kt x 8nt)
__device__ __align__(16) unsigned       g_w1p[8192];    // w1 B-frags (4kt x 32nt)
__device__ __align__(16) unsigned       g_w2p[8192];    // w2 B-frags (16kt x 8nt)

// -------- helpers --------
__device__ __forceinline__ unsigned pk(float lo, float hi) {
    __nv_bfloat162 t = __floats2bfloat162_rn(lo, hi);   // .x = lo (low 16 bits)
    return *reinterpret_cast<unsigned*>(&t);
}

__device__ __forceinline__ void mma_bf16(float* c, const unsigned* a, unsigned b0, unsigned b1) {
    asm volatile(
        "mma.sync.aligned.m16n8k16.row.col.f32.bf16.bf16.f32 "
        "{%0,%1,%2,%3}, {%4,%5,%6,%7}, {%8,%9}, {%0,%1,%2,%3};"
        : "+f"(c[0]), "+f"(c[1]), "+f"(c[2]), "+f"(c[3])
        : "r"(a[0]), "r"(a[1]), "r"(a[2]), "r"(a[3]), "r"(b0), "r"(b1));
}

// =========================================================
// K0: zero the x1 accumulator
// =========================================================
__global__ void k_zero() {
    float4* p = reinterpret_cast<float4*>(g_x1);
    const int n4 = NOC / 4;
    int i = blockIdx.x * blockDim.x + threadIdx.x;
    const int stride = gridDim.x * blockDim.x;
    const float4 z = make_float4(0.f, 0.f, 0.f, 0.f);
    for (; i < n4; i += stride) p[i] = z;
}

// =========================================================
// K1: fk[p][o][c] = (1/O) * sum_kd FKB[p,o,kd] * FW[kd,c]  -> bf16 pairs
// grid = 256 (p*16+o), block = 32 (channel pairs)
// =========================================================
__global__ void k_fk(const float* __restrict__ fkb, const float* __restrict__ fw) {
    __shared__ float s[KDD];
    const int po = blockIdx.x;
    const int t  = threadIdx.x;
    s[t]      = fkb[po * KDD + t];
    s[t + 32] = fkb[po * KDD + t + 32];
    __syncthreads();
    float a0 = 0.f, a1 = 0.f;
#pragma unroll 16
    for (int kd = 0; kd < KDD; kd++) {
        a0 += s[kd] * fw[kd * CC + 2 * t];
        a1 += s[kd] * fw[kd * CC + 2 * t + 1];
    }
    g_fkb[po * 32 + t] = __floats2bfloat162_rn(a0 * (1.0f / OO), a1 * (1.0f / OO));
}

// =========================================================
// K1b: pack kernel_w / w1 / w2 into mma B-fragment layout (bf16)
// B frag (m16n8k16): b0 = {B[k][n], B[k+1][n]}, k=(lane%4)*2, n=lane>>2; b1: k+=8
// =========================================================
__global__ void k_pack(const float* __restrict__ kw,
                       const float* __restrict__ w1,
                       const float* __restrict__ w2) {
    const int tid  = threadIdx.x;
    const int wrp  = tid >> 5, lane = tid & 31;
    const int g    = lane >> 2, tg = lane & 3;
    // kw [64,64]: 4kt x 8nt
    for (int f = wrp; f < 32; f += 8) {
        const int kt = f >> 3, nt = f & 7;
        const int k = kt * 16 + 2 * tg, n = nt * 8 + g;
        g_kwp[(f * 32 + lane) * 2 + 0] = pk(kw[k * 64 + n],      kw[(k + 1) * 64 + n]);
        g_kwp[(f * 32 + lane) * 2 + 1] = pk(kw[(k + 8) * 64 + n], kw[(k + 9) * 64 + n]);
    }
    // w1 [64,256]: 4kt x 32nt
    for (int f = wrp; f < 128; f += 8) {
        const int kt = f >> 5, nt = f & 31;
        const int k = kt * 16 + 2 * tg, n = nt * 8 + g;
        g_w1p[(f * 32 + lane) * 2 + 0] = pk(w1[k * 256 + n],       w1[(k + 1) * 256 + n]);
        g_w1p[(f * 32 + lane) * 2 + 1] = pk(w1[(k + 8) * 256 + n], w1[(k + 9) * 256 + n]);
    }
    // w2 [256,64]: 16kt x 8nt
    for (int f = wrp; f < 128; f += 8) {
        const int kt = f >> 3, nt = f & 7;
        const int k = kt * 16 + 2 * tg, n = nt * 8 + g;
        g_w2p[(f * 32 + lane) * 2 + 0] = pk(w2[k * 64 + n],       w2[(k + 1) * 64 + n]);
        g_w2p[(f * 32 + lane) * 2 + 1] = pk(w2[(k + 8) * 64 + n], w2[(k + 9) * 64 + n]);
    }
}

// =========================================================
// K2: edge conv via bf16 mma. One warp = one edge (16x64 = KB[16x64] @ W[64x64]).
// 8 warps/block, 4 edges/warp -> 32 edges/block, grid = 3125.
// Scatter: per-warp double-buffered cp.reduce.async.bulk (4KB/edge).
// =========================================================
__global__ void __launch_bounds__(256, 2) k_edge(
    const float* __restrict__ x,
    const float* __restrict__ kb,
    const int*   __restrict__ ei)
{
    extern __shared__ float sme[];
    unsigned* Wp  = (unsigned*)sme;   // 2048 uints = 8KB
    float*    MSG = sme + 2048;       // 8 warps x 2 x 1024 f32 = 64KB

    const int tid  = threadIdx.x;
    const int wrp  = tid >> 5, lane = tid & 31;
    const int g    = lane >> 2, tg = lane & 3;

    for (int i = tid; i < 2048; i += 256) Wp[i] = g_kwp[i];
    __syncthreads();

    float* msgbuf = MSG + wrp * 2048;

#pragma unroll 1
    for (int it = 0; it < 4; ++it) {
        const int e   = blockIdx.x * 32 + wrp * 4 + it;
        const int src = ei[e];
        const int dst = ei[EE + e];

        // ---- A fragments straight from gmem (fp32 -> bf16) ----
        unsigned A[4][4];
        const float* kbe = kb + (size_t)e * TILE;
#pragma unroll
        for (int kt = 0; kt < 4; ++kt) {
            const int k0 = kt * 16 + 2 * tg;
            float2 v;
            v = *(const float2*)(kbe + g * 64 + k0);            A[kt][0] = pk(v.x, v.y);
            v = *(const float2*)(kbe + (g + 8) * 64 + k0);      A[kt][1] = pk(v.x, v.y);
            v = *(const float2*)(kbe + g * 64 + k0 + 8);        A[kt][2] = pk(v.x, v.y);
            v = *(const float2*)(kbe + (g + 8) * 64 + k0 + 8);  A[kt][3] = pk(v.x, v.y);
        }

        float c[8][4];
#pragma unroll
        for (int nt = 0; nt < 8; ++nt)
            c[nt][0] = c[nt][1] = c[nt][2] = c[nt][3] = 0.f;
#pragma unroll
        for (int kt = 0; kt < 4; ++kt)
#pragma unroll
            for (int nt = 0; nt < 8; ++nt) {
                uint2 b = *(const uint2*)&Wp[((kt * 8 + nt) * 32 + lane) * 2];
                mma_bf16(c[nt], A[kt], b.x, b.y);
            }

        // ---- buffer management ----
        const int buf = it & 1;
        float* mb = msgbuf + buf * 1024;
        __syncwarp();
        if (lane == 0 && it >= 2)
            asm volatile("cp.async.bulk.wait_group 1;" ::: "memory");
        __syncwarp();

        // ---- msg = x[src] * K, staged to smem ----
        const float* xs = x + (size_t)src * TILE;
#pragma unroll
        for (int nt = 0; nt < 8; ++nt) {
            const int col = nt * 8 + 2 * tg;
            float2 x0 = *(const float2*)(xs + g * 64 + col);
            float2 x1 = *(const float2*)(xs + (g + 8) * 64 + col);
            *(float2*)(mb + g * 64 + col)       = make_float2(c[nt][0] * x0.x, c[nt][1] * x0.y);
            *(float2*)(mb + (g + 8) * 64 + col) = make_float2(c[nt][2] * x1.x, c[nt][3] * x1.y);
        }
        __syncwarp();

        if (lane == 0) {
            asm volatile("fence.proxy.async.shared::cta;" ::: "memory");
            unsigned saddr = (unsigned)__cvta_generic_to_shared(mb);
            float* gptr = g_x1 + (size_t)dst * TILE;
            asm volatile(
                "cp.reduce.async.bulk.global.shared::cta.bulk_group.add.f32 [%0], [%1], %2;"
                :: "l"(gptr), "r"(saddr), "r"(4096) : "memory");
            asm volatile("cp.async.bulk.commit_group;" ::: "memory");
        }
    }
    if (lane == 0)
        asm volatile("cp.async.bulk.wait_group 0;" ::: "memory");
    __syncwarp();
}

// =========================================================
// K3: fused fiber conv + LN + bf16-MMA MLP + layer-scale + residual
// block = 256 threads (8 warps), 16 nodes/block in 2 groups of 8.
// Within a group: warp w owns node (base+w): rows r0=16w+g, r0+8.
// h1 is warp-private -> no block barrier between MLP1 and MLP2.
// =========================================================
#define FUSE_SMEM_BYTES 203008

__global__ void __launch_bounds__(256) k_fuse(
    const float* __restrict__ x,
    const float* __restrict__ cb,
    const float* __restrict__ lns,
    const float* __restrict__ lnb,
    const float* __restrict__ b1,
    const float* __restrict__ b2,
    const float* __restrict__ ls,
    float*       __restrict__ out)
{
    extern __shared__ float sm[];
    __nv_bfloat16* fk_s = (__nv_bfloat16*)sm;          // 16384 bf16 (32KB)
    unsigned* w1p  = (unsigned*)(sm + 8192);           // 8192 u32 (32KB)
    unsigned* w2p  = w1p + 8192;                       // 8192 u32 (32KB)
    float* x2    = (float*)(w2p + 8192);               // 128 x 66 f32 (33KB)
    float* mu_s  = x2 + 8448;                          // 128
    float* rs_s  = mu_s + 128;                         // 128
    float* b1_s  = rs_s + 128;                         // 256
    float* b2_s  = b1_s + 256;                         // 64
    float* ls_s  = b2_s + 64;                          // 64
    float* lns_s = ls_s + 64;                          // 64
    float* lnb_s = lns_s + 64;                         // 64
    float* cb_s  = lnb_s + 64;                         // 64
    unsigned* h1 = (unsigned*)(cb_s + 64);             // 128 x 132 u32 (66KB)

    const int tid  = threadIdx.x;
    const int wrp  = tid >> 5, lane = tid & 31;
    const int g    = lane >> 2, tg = lane & 3;

    for (int i = tid; i < 8192; i += 256) {
        ((__nv_bfloat162*)fk_s)[i] = g_fkb[i];
        w1p[i] = g_w1p[i];
        w2p[i] = g_w2p[i];
    }
    if (tid < 64) {
        b2_s[tid]  = b2[tid];
        ls_s[tid]  = ls[tid] * 1e-6f;   // fold LS_VAL
        lns_s[tid] = lns[tid];
        lnb_s[tid] = lnb[tid];
        cb_s[tid]  = cb[tid];
    }
    b1_s[tid] = b1[tid];
    __syncthreads();

    const int c_ = tid & 63, pg = tid >> 6;

#pragma unroll 1
    for (int grp = 0; grp < 2; ++grp) {
        const int nodebase = blockIdx.x * 16 + grp * 8;

        // ---- fiber conv: x2[row=n*16+p][c] = cb[c] + sum_o x1[n,o,c]*fk[p,o,c] ----
#pragma unroll 1
        for (int n = 0; n < 8; ++n) {
            const float* x1p = g_x1 + (size_t)(nodebase + n) * TILE;
            float xr[16];
#pragma unroll
            for (int o = 0; o < 16; ++o) xr[o] = x1p[o * 64 + c_];
#pragma unroll
            for (int i = 0; i < 4; ++i) {
                const int p = pg * 4 + i;
                float a = cb_s[c_];
#pragma unroll
                for (int o = 0; o < 16; ++o)
                    a += xr[o] * __bfloat162float(fk_s[p * 1024 + o * 64 + c_]);
                x2[(n * 16 + p) * 66 + c_] = a;
            }
        }
        __syncthreads();

        // ---- LayerNorm params: 2 threads per row ----
        {
            const int row = tid >> 1, q = tid & 1;
            const float* xr = x2 + row * 66 + q * 32;
            float s = 0.f, ss = 0.f;
#pragma unroll
            for (int i = 0; i < 32; ++i) { float v = xr[i]; s += v; ss += v * v; }
            s  += __shfl_xor_sync(0xffffffffu, s, 1);
            ss += __shfl_xor_sync(0xffffffffu, ss, 1);
            const float mu  = s * (1.f / 64.f);
            const float var = ss * (1.f / 64.f) - mu * mu;
            if (q == 0) { mu_s[row] = mu; rs_s[row] = rsqrtf(var + 1e-6f); }
        }
        __syncthreads();

        // ---- build normalized A fragments (bf16) for MLP1 ----
        const int r0  = wrp * 16 + g;
        const float mu0 = mu_s[r0],     rs0 = rs_s[r0];
        const float mu1 = mu_s[r0 + 8], rs1 = rs_s[r0 + 8];
        unsigned A[4][4];
#pragma unroll
        for (int kt = 0; kt < 4; ++kt) {
            const int k0 = kt * 16 + 2 * tg;
            float2 sc0 = *(float2*)(lns_s + k0),     bi0 = *(float2*)(lnb_s + k0);
            float2 sc1 = *(float2*)(lns_s + k0 + 8), bi1 = *(float2*)(lnb_s + k0 + 8);
            float2 v;
            v = *(float2*)(x2 + r0 * 66 + k0);
            A[kt][0] = pk((v.x - mu0) * rs0 * sc0.x + bi0.x, (v.y - mu0) * rs0 * sc0.y + bi0.y);
            v = *(float2*)(x2 + (r0 + 8) * 66 + k0);
            A[kt][1] = pk((v.x - mu1) * rs1 * sc0.x + bi0.x, (v.y - mu1) * rs1 * sc0.y + bi0.y);
            v = *(float2*)(x2 + r0 * 66 + k0 + 8);
            A[kt][2] = pk((v.x - mu0) * rs0 * sc1.x + bi1.x, (v.y - mu0) * rs0 * sc1.y + bi1.y);
            v = *(float2*)(x2 + (r0 + 8) * 66 + k0 + 8);
            A[kt][3] = pk((v.x - mu1) * rs1 * sc1.x + bi1.x, (v.y - mu1) * rs1 * sc1.y + bi1.y);
        }

        // ---- MLP1: [16 x 64] @ [64 x 256] -> relu -> h1 (bf16, frag-packed) ----
#pragma unroll 1
        for (int half = 0; half < 2; ++half) {
            float c1r[16][4];
#pragma unroll
            for (int nt = 0; nt < 16; ++nt) {
                const int col = (half * 16 + nt) * 8 + 2 * tg;
                c1r[nt][0] = b1_s[col]; c1r[nt][1] = b1_s[col + 1];
                c1r[nt][2] = b1_s[col]; c1r[nt][3] = b1_s[col + 1];
            }
#pragma unroll
            for (int kt = 0; kt < 4; ++kt)
#pragma unroll
                for (int nt = 0; nt < 16; ++nt) {
                    const int ntg = half * 16 + nt;
                    uint2 b = *(const uint2*)&w1p[((kt * 32 + ntg) * 32 + lane) * 2];
                    mma_bf16(c1r[nt], A[kt], b.x, b.y);
                }
#pragma unroll
            for (int nt = 0; nt < 16; ++nt) {
                const int ntg = half * 16 + nt;
                const float p0 = fmaxf(c1r[nt][0], 0.f), p1 = fmaxf(c1r[nt][1], 0.f);
                const float p2 = fmaxf(c1r[nt][2], 0.f), p3 = fmaxf(c1r[nt][3], 0.f);
                h1[r0 * 132 + ntg * 4 + tg]       = pk(p0, p1);
                h1[(r0 + 8) * 132 + ntg * 4 + tg] = pk(p2, p3);
            }
        }
        __syncwarp();   // h1 is warp-private; cross-lane visibility only

        // ---- MLP2: [16 x 256] @ [256 x 64] ----
        float d[8][4];
#pragma unroll
        for (int nt = 0; nt < 8; ++nt) {
            const int col = nt * 8 + 2 * tg;
            d[nt][0] = b2_s[col]; d[nt][1] = b2_s[col + 1];
            d[nt][2] = b2_s[col]; d[nt][3] = b2_s[col + 1];
        }
#pragma unroll
        for (int kt = 0; kt < 16; ++kt) {
            unsigned a[4];
            a[0] = h1[r0 * 132 + kt * 8 + tg];
            a[1] = h1[(r0 + 8) * 132 + kt * 8 + tg];
            a[2] = h1[r0 * 132 + kt * 8 + 4 + tg];
            a[3] = h1[(r0 + 8) * 132 + kt * 8 + 4 + tg];
#pragma unroll
            for (int nt = 0; nt < 8; ++nt) {
                uint2 b = *(const uint2*)&w2p[((kt * 8 + nt) * 32 + lane) * 2];
                mma_bf16(d[nt], a, b.x, b.y);
            }
        }

        // ---- epilogue: out = ls * d + x ----
        const int node = nodebase + wrp;
        const float* xres = x + (size_t)node * TILE;
        float* op = out + (size_t)node * TILE;
#pragma unroll
        for (int nt = 0; nt < 8; ++nt) {
            const int col = nt * 8 + 2 * tg;
            float2 xv0 = *(const float2*)(xres + g * 64 + col);
            float2 xv1 = *(const float2*)(xres + (g + 8) * 64 + col);
            *(float2*)(op + g * 64 + col) =
                make_float2(ls_s[col] * d[nt][0] + xv0.x, ls_s[col + 1] * d[nt][1] + xv0.y);
            *(float2*)(op + (g + 8) * 64 + col) =
                make_float2(ls_s[col] * d[nt][2] + xv1.x, ls_s[col + 1] * d[nt][3] + xv1.y);
        }
        __syncthreads();   // protect x2 for next group
    }
}

// =========================================================
extern "C" void kernel_launch(void* const* d_in, const int* in_sizes, int n_in,
                              void* d_out, int out_size)
{
    (void)in_sizes; (void)n_in; (void)out_size;
    const float* x   = (const float*)d_in[0];
    const float* kb  = (const float*)d_in[1];
    const float* fkb = (const float*)d_in[2];
    const int*   ei  = (const int*)  d_in[3];
    const float* kw  = (const float*)d_in[4];
    const float* fkw = (const float*)d_in[5];
    const float* cb  = (const float*)d_in[6];
    const float* lns = (const float*)d_in[7];
    const float* lnb = (const float*)d_in[8];
    const float* w1  = (const float*)d_in[9];
    const float* b1  = (const float*)d_in[10];
    const float* w2  = (const float*)d_in[11];
    const float* b2  = (const float*)d_in[12];
    const float* ls  = (const float*)d_in[13];
    float* out = (float*)d_out;

    cudaFuncSetAttribute(k_edge, cudaFuncAttributeMaxDynamicSharedMemorySize, 73728);
    cudaFuncSetAttribute(k_fuse, cudaFuncAttributeMaxDynamicSharedMemorySize, FUSE_SMEM_BYTES);

    k_zero<<<2560, 256>>>();
    k_fk<<<OO * OO, 32>>>(fkb, fkw);
    k_pack<<<1, 256>>>(kw, w1, w2);
    k_edge<<<EE / 32, 256, 73728>>>(x, kb, ei);
    k_fuse<<<NN / 16, 256, FUSE_SMEM_BYTES>>>(x, cb, lns, lnb, b1, b2, ls, out);
}

// round 6
// speedup vs baseline: 5.2269x; 1.1065x over previous
#include <cuda_runtime.h>
#include <cuda_bf16.h>

#define NN   10000
#define OO   16
#define CC   64
#define EE   100000
#define KDD  64
#define NOC  (NN*OO*CC)          // 10,240,000
#define TILE (OO*CC)             // 1024 floats = 4KB per node/edge tile

// column permutation applied to g_x1 tiles (word index within a 64-word row)
#define PERM(row, col) ((col) ^ (((row) & 3) << 3))

// -------- device scratch (no allocations allowed) --------
__device__ __align__(16) float          g_x1[NOC];      // 41 MB spatial-conv accumulator (PERMuted cols)
__device__ __align__(16) __nv_bfloat162 g_fkb[8192];    // fiber kernel bf16 (pre /O)
__device__ __align__(16) unsigned       g_kwp[2048];    // kernel_w  B-frags (4kt x 8nt)
__device__ __align__(16) unsigned       g_w1p[8192];    // w1 B-frags (4kt x 32nt)
__device__ __align__(16) unsigned       g_w2p[8192];    // w2 B-frags (16kt x 8nt)

// -------- helpers --------
__device__ __forceinline__ unsigned pk(float lo, float hi) {
    __nv_bfloat162 t = __floats2bfloat162_rn(lo, hi);   // .x = lo (low 16 bits)
    return *reinterpret_cast<unsigned*>(&t);
}

__device__ __forceinline__ void mma_bf16(float* c, const unsigned* a, unsigned b0, unsigned b1) {
    asm volatile(
        "mma.sync.aligned.m16n8k16.row.col.f32.bf16.bf16.f32 "
        "{%0,%1,%2,%3}, {%4,%5,%6,%7}, {%8,%9}, {%0,%1,%2,%3};"
        : "+f"(c[0]), "+f"(c[1]), "+f"(c[2]), "+f"(c[3])
        : "r"(a[0]), "r"(a[1]), "r"(a[2]), "r"(a[3]), "r"(b0), "r"(b1));
}

// =========================================================
// K0: zero the x1 accumulator
// =========================================================
__global__ void k_zero() {
    float4* p = reinterpret_cast<float4*>(g_x1);
    const int n4 = NOC / 4;
    int i = blockIdx.x * blockDim.x + threadIdx.x;
    const int stride = gridDim.x * blockDim.x;
    const float4 z = make_float4(0.f, 0.f, 0.f, 0.f);
    for (; i < n4; i += stride) p[i] = z;
}

// =========================================================
// K1: fk[p][o][c] = (1/O) * sum_kd FKB[p,o,kd] * FW[kd,c]  -> bf16 pairs
// =========================================================
__global__ void k_fk(const float* __restrict__ fkb, const float* __restrict__ fw) {
    __shared__ float s[KDD];
    const int po = blockIdx.x;
    const int t  = threadIdx.x;
    s[t]      = fkb[po * KDD + t];
    s[t + 32] = fkb[po * KDD + t + 32];
    __syncthreads();
    float a0 = 0.f, a1 = 0.f;
#pragma unroll 16
    for (int kd = 0; kd < KDD; kd++) {
        a0 += s[kd] * fw[kd * CC + 2 * t];
        a1 += s[kd] * fw[kd * CC + 2 * t + 1];
    }
    g_fkb[po * 32 + t] = __floats2bfloat162_rn(a0 * (1.0f / OO), a1 * (1.0f / OO));
}

// =========================================================
// K1b: pack kernel_w / w1 / w2 into mma B-fragment layout (bf16)
// =========================================================
__global__ void k_pack(const float* __restrict__ kw,
                       const float* __restrict__ w1,
                       const float* __restrict__ w2) {
    const int tid  = threadIdx.x;
    const int wrp  = tid >> 5, lane = tid & 31;
    const int g    = lane >> 2, tg = lane & 3;
    for (int f = wrp; f < 32; f += 8) {
        const int kt = f >> 3, nt = f & 7;
        const int k = kt * 16 + 2 * tg, n = nt * 8 + g;
        g_kwp[(f * 32 + lane) * 2 + 0] = pk(kw[k * 64 + n],       kw[(k + 1) * 64 + n]);
        g_kwp[(f * 32 + lane) * 2 + 1] = pk(kw[(k + 8) * 64 + n], kw[(k + 9) * 64 + n]);
    }
    for (int f = wrp; f < 128; f += 8) {
        const int kt = f >> 5, nt = f & 31;
        const int k = kt * 16 + 2 * tg, n = nt * 8 + g;
        g_w1p[(f * 32 + lane) * 2 + 0] = pk(w1[k * 256 + n],       w1[(k + 1) * 256 + n]);
        g_w1p[(f * 32 + lane) * 2 + 1] = pk(w1[(k + 8) * 256 + n], w1[(k + 9) * 256 + n]);
    }
    for (int f = wrp; f < 128; f += 8) {
        const int kt = f >> 3, nt = f & 7;
        const int k = kt * 16 + 2 * tg, n = nt * 8 + g;
        g_w2p[(f * 32 + lane) * 2 + 0] = pk(w2[k * 64 + n],       w2[(k + 1) * 64 + n]);
        g_w2p[(f * 32 + lane) * 2 + 1] = pk(w2[(k + 8) * 64 + n], w2[(k + 9) * 64 + n]);
    }
}

// =========================================================
// K2: edge conv, coalesced loads + ldmatrix + permuted msg layout.
// 8 warps/block, 4 edges/warp, grid=3125, smem=88KB, 2 blocks/SM.
// =========================================================
__global__ void __launch_bounds__(256, 2) k_edge(
    const float* __restrict__ x,
    const float* __restrict__ kb,
    const int*   __restrict__ ei)
{
    extern __shared__ float sme[];
    unsigned* Wp      = (unsigned*)sme;             // 2048 u32 (8KB)
    unsigned* KBS_all = Wp + 2048;                  // 8 x 512 u32 (16KB) bf16 tiles
    float*    MSG_all = (float*)(KBS_all + 4096);   // 8 x 2048 f32 (64KB)

    const int tid  = threadIdx.x;
    const int wrp  = tid >> 5, lane = tid & 31;
    const int g    = lane >> 2, tg = lane & 3;

    for (int i = tid; i < 2048; i += 256) Wp[i] = g_kwp[i];
    __syncthreads();

    char*  KBS = (char*)(KBS_all + wrp * 512);      // 2KB bf16 tile, swizzled
    float* MSG = MSG_all + wrp * 2048;

    // ldmatrix source address (per-lane, per-kt constant part)
    const int lrow  = lane & 15;
    const int lhalf = lane >> 4;
    const unsigned kbs_base = (unsigned)__cvta_generic_to_shared(KBS);

#pragma unroll 1
    for (int it = 0; it < 4; ++it) {
        const int e   = blockIdx.x * 32 + wrp * 4 + it;
        const int src = ei[e];
        const int dst = ei[EE + e];

        // ---- coalesced loads ----
        const float4* kb4 = (const float4*)(kb + (size_t)e * TILE);
        const float4* x4  = (const float4*)(x  + (size_t)src * TILE);
        float4 kv[8], xv[8];
#pragma unroll
        for (int i = 0; i < 8; ++i) kv[i] = kb4[i * 32 + lane];
#pragma unroll
        for (int i = 0; i < 8; ++i) xv[i] = x4[i * 32 + lane];

        // ---- kb -> bf16 swizzled smem (KBS free: prev ldmatrix done) ----
#pragma unroll
        for (int i = 0; i < 8; ++i) {
            const int idx = i * 32 + lane;          // float4 index in tile
            const int row = idx >> 4;               // 0..15
            const int bc  = (idx & 15) * 8;         // byte col (0..120)
            const int bcs = bc ^ ((row & 7) << 4);  // SW128 swizzle
            uint2 v;
            v.x = pk(kv[i].x, kv[i].y);
            v.y = pk(kv[i].z, kv[i].w);
            *(uint2*)(KBS + row * 128 + bcs) = v;
        }

        const int buf = it & 1;
        float* mb = MSG + buf * 1024;
        if (lane == 0 && it >= 2)
            asm volatile("cp.async.bulk.wait_group 1;" ::: "memory");
        __syncwarp();

        // ---- x -> MSG buffer (permuted cols), in-place staging ----
#pragma unroll
        for (int i = 0; i < 8; ++i) {
            const int f    = (i * 32 + lane) * 4;   // word index
            const int row  = f >> 6;
            const int colw = f & 63;
            *(float4*)(mb + row * 64 + PERM(row, colw)) = xv[i];
        }
        __syncwarp();

        // ---- A fragments via ldmatrix ----
        unsigned A[4][4];
#pragma unroll
        for (int kt = 0; kt < 4; ++kt) {
            const int bc  = kt * 32 + lhalf * 16;
            const unsigned addr = kbs_base + lrow * 128 + (bc ^ ((lrow & 7) << 4));
            asm volatile(
                "ldmatrix.sync.aligned.m8n8.x4.shared.b16 {%0,%1,%2,%3}, [%4];"
                : "=r"(A[kt][0]), "=r"(A[kt][1]), "=r"(A[kt][2]), "=r"(A[kt][3])
                : "r"(addr));
        }

        float c[8][4];
#pragma unroll
        for (int nt = 0; nt < 8; ++nt)
            c[nt][0] = c[nt][1] = c[nt][2] = c[nt][3] = 0.f;
#pragma unroll
        for (int kt = 0; kt < 4; ++kt)
#pragma unroll
            for (int nt = 0; nt < 8; ++nt) {
                uint2 b = *(const uint2*)&Wp[((kt * 8 + nt) * 32 + lane) * 2];
                mma_bf16(c[nt], A[kt], b.x, b.y);
            }

        // ---- msg = x * k, in place (2-phase thanks to PERM) ----
#pragma unroll
        for (int nt = 0; nt < 8; ++nt) {
            const int c0 = nt * 8 + 2 * tg;
            const int pc = PERM(g, c0);             // (g+8)&3 == g&3
            float2 a0 = *(float2*)(mb + g * 64 + pc);
            float2 a1 = *(float2*)(mb + (g + 8) * 64 + pc);
            *(float2*)(mb + g * 64 + pc)       = make_float2(a0.x * c[nt][0], a0.y * c[nt][1]);
            *(float2*)(mb + (g + 8) * 64 + pc) = make_float2(a1.x * c[nt][2], a1.y * c[nt][3]);
        }
        __syncwarp();

        if (lane == 0) {
            asm volatile("fence.proxy.async.shared::cta;" ::: "memory");
            unsigned saddr = (unsigned)__cvta_generic_to_shared(mb);
            float* gptr = g_x1 + (size_t)dst * TILE;
            asm volatile(
                "cp.reduce.async.bulk.global.shared::cta.bulk_group.add.f32 [%0], [%1], %2;"
                :: "l"(gptr), "r"(saddr), "r"(4096) : "memory");
            asm volatile("cp.async.bulk.commit_group;" ::: "memory");
        }
    }
    if (lane == 0)
        asm volatile("cp.async.bulk.wait_group 0;" ::: "memory");
    __syncwarp();
}

// =========================================================
// K3: fused fiber conv + LN + bf16-MMA MLP + layer-scale + residual
// 512 threads (16 warps), 16 nodes/block (2 groups of 8), 2 warps/node.
// =========================================================
#define FUSE_SMEM_BYTES 203008

__global__ void __launch_bounds__(512, 1) k_fuse(
    const float* __restrict__ x,
    const float* __restrict__ cb,
    const float* __restrict__ lns,
    const float* __restrict__ lnb,
    const float* __restrict__ b1,
    const float* __restrict__ b2,
    const float* __restrict__ ls,
    float*       __restrict__ out)
{
    extern __shared__ float sm[];
    unsigned* w1p  = (unsigned*)sm;                    // 8192 u32 (32KB)
    unsigned* w2p  = w1p + 8192;                       // 8192 u32 (32KB)
    unsigned* fkp  = w2p + 8192;                       // 8192 u32 = bf162 (32KB)
    float* x2    = (float*)(fkp + 8192);               // 128 x 66 f32 (33KB)
    float* mu_s  = x2 + 8448;                          // 128
    float* rs_s  = mu_s + 128;                         // 128
    float* b1_s  = rs_s + 128;                         // 256
    float* b2_s  = b1_s + 256;                         // 64
    float* ls_s  = b2_s + 64;                          // 64
    float* lns_s = ls_s + 64;                          // 64
    float* lnb_s = lns_s + 64;                         // 64
    float* cb_s  = lnb_s + 64;                         // 64
    unsigned* h1 = (unsigned*)(cb_s + 64);             // 128 x 132 u32 (66KB)
    float* stage = (float*)h1;                         // alias: 8192 f32 x1 staging

    const int tid  = threadIdx.x;
    const int wrp  = tid >> 5, lane = tid & 31;
    const int g    = lane >> 2, tg = lane & 3;
    const int nloc = wrp >> 1;        // 0..7: node within group
    const int sub  = wrp & 1;         // warp's half of the MLP

    for (int i = tid; i < 8192; i += 512) {
        w1p[i] = g_w1p[i];
        w2p[i] = g_w2p[i];
        fkp[i] = ((const unsigned*)g_fkb)[i];
    }
    if (tid < 64) {
        b2_s[tid]  = b2[tid];
        ls_s[tid]  = ls[tid] * 1e-6f;   // fold LS_VAL
        lns_s[tid] = lns[tid];
        lnb_s[tid] = lnb[tid];
        cb_s[tid]  = cb[tid];
    }
    if (tid < 256) b1_s[tid] = b1[tid];
    __syncthreads();

#pragma unroll 1
    for (int grp = 0; grp < 2; ++grp) {
        const int nodebase = blockIdx.x * 16 + grp * 8;

        // ---- stage x1 of 8 nodes (coalesced, permuted layout preserved) ----
        {
            const float4* s4 = (const float4*)(g_x1 + (size_t)nodebase * TILE);
            float4* d4 = (float4*)stage;
            for (int i = tid; i < 2048; i += 512) d4[i] = s4[i];
        }
        __syncthreads();

        // ---- fiber conv (bf162 hfma2): thread = (c-pair, p) ----
        {
            const int c2 = tid & 31, p = tid >> 5;
            const float2 cbv = *(const float2*)(cb_s + 2 * c2);
#pragma unroll 1
            for (int n = 0; n < 8; ++n) {
                const float* sp = stage + n * 1024;
                __nv_bfloat162 acc = __floats2bfloat162_rn(0.f, 0.f);
#pragma unroll
                for (int o = 0; o < 16; ++o) {
                    float2 xv = *(const float2*)(sp + o * 64 + PERM(o, 2 * c2));
                    __nv_bfloat162 fk = ((const __nv_bfloat162*)fkp)[p * 512 + o * 32 + c2];
                    acc = __hfma2(__float22bfloat162_rn(xv), fk, acc);
                }
                float2 a = __bfloat1622float2(acc);
                *(float2*)(x2 + (n * 16 + p) * 66 + 2 * c2) =
                    make_float2(a.x + cbv.x, a.y + cbv.y);
            }
        }
        __syncthreads();

        // ---- LayerNorm stats: 4 threads per row (float2 loads: row*66 is
        //      only 8B-aligned for odd rows, float4 would trap) ----
        {
            const int row = tid >> 2, q = tid & 3;
            const float* xr = x2 + row * 66 + q * 16;
            float s = 0.f, ss = 0.f;
#pragma unroll
            for (int j = 0; j < 8; ++j) {
                float2 v = *(const float2*)(xr + j * 2);
                s  += v.x + v.y;
                ss += v.x * v.x + v.y * v.y;
            }
            s  += __shfl_xor_sync(0xffffffffu, s, 1);
            ss += __shfl_xor_sync(0xffffffffu, ss, 1);
            s  += __shfl_xor_sync(0xffffffffu, s, 2);
            ss += __shfl_xor_sync(0xffffffffu, ss, 2);
            if (q == 0) {
                const float mu  = s * (1.f / 64.f);
                const float var = ss * (1.f / 64.f) - mu * mu;
                mu_s[row] = mu;
                rs_s[row] = rsqrtf(var + 1e-6f);
            }
        }
        __syncthreads();

        // ---- build normalized A fragments (both warps of a node build same A) ----
        const int r0  = nloc * 16 + g;
        const float mu0 = mu_s[r0],     rs0 = rs_s[r0];
        const float mu1 = mu_s[r0 + 8], rs1 = rs_s[r0 + 8];
        unsigned A[4][4];
#pragma unroll
        for (int kt = 0; kt < 4; ++kt) {
            const int k0 = kt * 16 + 2 * tg;
            float2 sc0 = *(float2*)(lns_s + k0),     bi0 = *(float2*)(lnb_s + k0);
            float2 sc1 = *(float2*)(lns_s + k0 + 8), bi1 = *(float2*)(lnb_s + k0 + 8);
            float2 v;
            v = *(float2*)(x2 + r0 * 66 + k0);
            A[kt][0] = pk((v.x - mu0) * rs0 * sc0.x + bi0.x, (v.y - mu0) * rs0 * sc0.y + bi0.y);
            v = *(float2*)(x2 + (r0 + 8) * 66 + k0);
            A[kt][1] = pk((v.x - mu1) * rs1 * sc0.x + bi0.x, (v.y - mu1) * rs1 * sc0.y + bi0.y);
            v = *(float2*)(x2 + r0 * 66 + k0 + 8);
            A[kt][2] = pk((v.x - mu0) * rs0 * sc1.x + bi1.x, (v.y - mu0) * rs0 * sc1.y + bi1.y);
            v = *(float2*)(x2 + (r0 + 8) * 66 + k0 + 8);
            A[kt][3] = pk((v.x - mu1) * rs1 * sc1.x + bi1.x, (v.y - mu1) * rs1 * sc1.y + bi1.y);
        }

        // ---- MLP1: this warp's half (16 of 32 n-tiles) ----
        {
            float c1r[16][4];
#pragma unroll
            for (int nt = 0; nt < 16; ++nt) {
                const int col = (sub * 16 + nt) * 8 + 2 * tg;
                c1r[nt][0] = b1_s[col]; c1r[nt][1] = b1_s[col + 1];
                c1r[nt][2] = b1_s[col]; c1r[nt][3] = b1_s[col + 1];
            }
#pragma unroll
            for (int kt = 0; kt < 4; ++kt)
#pragma unroll
                for (int nt = 0; nt < 16; ++nt) {
                    const int ntg = sub * 16 + nt;
                    uint2 b = *(const uint2*)&w1p[((kt * 32 + ntg) * 32 + lane) * 2];
                    mma_bf16(c1r[nt], A[kt], b.x, b.y);
                }
#pragma unroll
            for (int nt = 0; nt < 16; ++nt) {
                const int ntg = sub * 16 + nt;
                const float p0 = fmaxf(c1r[nt][0], 0.f), p1 = fmaxf(c1r[nt][1], 0.f);
                const float p2 = fmaxf(c1r[nt][2], 0.f), p3 = fmaxf(c1r[nt][3], 0.f);
                h1[r0 * 132 + ntg * 4 + tg]       = pk(p0, p1);
                h1[(r0 + 8) * 132 + ntg * 4 + tg] = pk(p2, p3);
            }
        }
        __syncthreads();   // h1 complete across each node's warp pair

        // ---- MLP2: this warp's quarter (4 of 8 n-tiles) ----
        float d[4][4];
#pragma unroll
        for (int nt = 0; nt < 4; ++nt) {
            const int col = (sub * 4 + nt) * 8 + 2 * tg;
            d[nt][0] = b2_s[col]; d[nt][1] = b2_s[col + 1];
            d[nt][2] = b2_s[col]; d[nt][3] = b2_s[col + 1];
        }
#pragma unroll
        for (int kt = 0; kt < 16; ++kt) {
            unsigned a[4];
            a[0] = h1[r0 * 132 + kt * 8 + tg];
            a[1] = h1[(r0 + 8) * 132 + kt * 8 + tg];
            a[2] = h1[r0 * 132 + kt * 8 + 4 + tg];
            a[3] = h1[(r0 + 8) * 132 + kt * 8 + 4 + tg];
#pragma unroll
            for (int nt = 0; nt < 4; ++nt) {
                uint2 b = *(const uint2*)&w2p[((kt * 8 + sub * 4 + nt) * 32 + lane) * 2];
                mma_bf16(d[nt], a, b.x, b.y);
            }
        }

        // ---- epilogue: out = ls * d + x ----
        {
            const int node = nodebase + nloc;
            const float* xres = x + (size_t)node * TILE;
            float* op = out + (size_t)node * TILE;
#pragma unroll
            for (int nt = 0; nt < 4; ++nt) {
                const int col = (sub * 4 + nt) * 8 + 2 * tg;
                float2 xv0 = *(const float2*)(xres + g * 64 + col);
                float2 xv1 = *(const float2*)(xres + (g + 8) * 64 + col);
                *(float2*)(op + g * 64 + col) =
                    make_float2(ls_s[col] * d[nt][0] + xv0.x, ls_s[col + 1] * d[nt][1] + xv0.y);
                *(float2*)(op + (g + 8) * 64 + col) =
                    make_float2(ls_s[col] * d[nt][2] + xv1.x, ls_s[col + 1] * d[nt][3] + xv1.y);
            }
        }
        __syncthreads();   // protect x2/h1/stage for next group
    }
}

// =========================================================
extern "C" void kernel_launch(void* const* d_in, const int* in_sizes, int n_in,
                              void* d_out, int out_size)
{
    (void)in_sizes; (void)n_in; (void)out_size;
    const float* x   = (const float*)d_in[0];
    const float* kb  = (const float*)d_in[1];
    const float* fkb = (const float*)d_in[2];
    const int*   ei  = (const int*)  d_in[3];
    const float* kw  = (const float*)d_in[4];
    const float* fkw = (const float*)d_in[5];
    const float* cb  = (const float*)d_in[6];
    const float* lns = (const float*)d_in[7];
    const float* lnb = (const float*)d_in[8];
    const float* w1  = (const float*)d_in[9];
    const float* b1  = (const float*)d_in[10];
    const float* w2  = (const float*)d_in[11];
    const float* b2  = (const float*)d_in[12];
    const float* ls  = (const float*)d_in[13];
    float* out = (float*)d_out;

    const int edge_smem = 90112;   // 88KB
    cudaFuncSetAttribute(k_edge, cudaFuncAttributeMaxDynamicSharedMemorySize, edge_smem);
    cudaFuncSetAttribute(k_fuse, cudaFuncAttributeMaxDynamicSharedMemorySize, FUSE_SMEM_BYTES);

    k_zero<<<2560, 256>>>();
    k_fk<<<OO * OO, 32>>>(fkb, fkw);
    k_pack<<<1, 256>>>(kw, w1, w2);
    k_edge<<<EE / 32, 256, edge_smem>>>(x, kb, ei);
    k_fuse<<<NN / 16, 512, FUSE_SMEM_BYTES>>>(x, cb, lns, lnb, b1, b2, ls, out);
}

// round 10
// speedup vs baseline: 6.6030x; 1.2633x over previous
#include <cuda_runtime.h>
#include <cuda_bf16.h>

#define NN   10000
#define OO   16
#define CC   64
#define EE   100000
#define KDD  64
#define NOC  (NN*OO*CC)          // 10,240,000
#define TILE (OO*CC)             // 1024 elements per node/edge tile

// column permutation applied to g_x1 tiles (element index within a 64-elem row)
#define PERM(row, col) ((col) ^ (((row) & 3) << 3))

// -------- device scratch (no allocations allowed) --------
__device__ __align__(16) __nv_bfloat16  g_x1[NOC];      // 20.5 MB spatial-conv accumulator (bf16, PERMuted)
__device__ __align__(16) __nv_bfloat162 g_fkb[8192];    // fiber kernel bf16 (pre /O)
__device__ __align__(16) unsigned       g_kwp[2048];    // kernel_w  B-frags (4kt x 8nt)
__device__ __align__(16) unsigned       g_w1p[8192];    // w1 B-frags (4kt x 32nt)
__device__ __align__(16) unsigned       g_w2p[8192];    // w2 B-frags (16kt x 8nt)

// -------- helpers --------
__device__ __forceinline__ unsigned pk(float lo, float hi) {
    __nv_bfloat162 t = __floats2bfloat162_rn(lo, hi);   // .x = lo (low 16 bits)
    return *reinterpret_cast<unsigned*>(&t);
}

__device__ __forceinline__ void mma_bf16(float* c, const unsigned* a, unsigned b0, unsigned b1) {
    asm volatile(
        "mma.sync.aligned.m16n8k16.row.col.f32.bf16.bf16.f32 "
        "{%0,%1,%2,%3}, {%4,%5,%6,%7}, {%8,%9}, {%0,%1,%2,%3};"
        : "+f"(c[0]), "+f"(c[1]), "+f"(c[2]), "+f"(c[3])
        : "r"(a[0]), "r"(a[1]), "r"(a[2]), "r"(a[3]), "r"(b0), "r"(b1));
}

// =========================================================
// K0: zero the bf16 x1 accumulator (20.5 MB)
// =========================================================
__global__ void k_zero() {
    uint4* p = reinterpret_cast<uint4*>(g_x1);
    const int n16 = NOC * 2 / 16;    // 1,280,000
    int i = blockIdx.x * blockDim.x + threadIdx.x;
    const int stride = gridDim.x * blockDim.x;
    const uint4 z = make_uint4(0u, 0u, 0u, 0u);
    for (; i < n16; i += stride) p[i] = z;
}

// =========================================================
// K1: fk[p][o][c] = (1/O) * sum_kd FKB[p,o,kd] * FW[kd,c]  -> bf16 pairs
// =========================================================
__global__ void k_fk(const float* __restrict__ fkb, const float* __restrict__ fw) {
    __shared__ float s[KDD];
    const int po = blockIdx.x;
    const int t  = threadIdx.x;
    s[t]      = fkb[po * KDD + t];
    s[t + 32] = fkb[po * KDD + t + 32];
    __syncthreads();
    float a0 = 0.f, a1 = 0.f;
#pragma unroll 16
    for (int kd = 0; kd < KDD; kd++) {
        a0 += s[kd] * fw[kd * CC + 2 * t];
        a1 += s[kd] * fw[kd * CC + 2 * t + 1];
    }
    g_fkb[po * 32 + t] = __floats2bfloat162_rn(a0 * (1.0f / OO), a1 * (1.0f / OO));
}

// =========================================================
// K1b: pack kernel_w / w1 / w2 into mma B-fragment layout (bf16)
// =========================================================
__global__ void k_pack(const float* __restrict__ kw,
                       const float* __restrict__ w1,
                       const float* __restrict__ w2) {
    const int tid  = threadIdx.x;
    const int wrp  = tid >> 5, lane = tid & 31;
    const int g    = lane >> 2, tg = lane & 3;
    for (int f = wrp; f < 32; f += 8) {
        const int kt = f >> 3, nt = f & 7;
        const int k = kt * 16 + 2 * tg, n = nt * 8 + g;
        g_kwp[(f * 32 + lane) * 2 + 0] = pk(kw[k * 64 + n],       kw[(k + 1) * 64 + n]);
        g_kwp[(f * 32 + lane) * 2 + 1] = pk(kw[(k + 8) * 64 + n], kw[(k + 9) * 64 + n]);
    }
    for (int f = wrp; f < 128; f += 8) {
        const int kt = f >> 5, nt = f & 31;
        const int k = kt * 16 + 2 * tg, n = nt * 8 + g;
        g_w1p[(f * 32 + lane) * 2 + 0] = pk(w1[k * 256 + n],       w1[(k + 1) * 256 + n]);
        g_w1p[(f * 32 + lane) * 2 + 1] = pk(w1[(k + 8) * 256 + n], w1[(k + 9) * 256 + n]);
    }
    for (int f = wrp; f < 128; f += 8) {
        const int kt = f >> 3, nt = f & 7;
        const int k = kt * 16 + 2 * tg, n = nt * 8 + g;
        g_w2p[(f * 32 + lane) * 2 + 0] = pk(w2[k * 64 + n],       w2[(k + 1) * 64 + n]);
        g_w2p[(f * 32 + lane) * 2 + 1] = pk(w2[(k + 8) * 64 + n], w2[(k + 9) * 64 + n]);
    }
}

// =========================================================
// K2: edge conv. kb stream loaded with L2::evict_first (protect x/x1 L2
// residency), msg scattered as bf16 (2KB/edge bulk-reduce add.noftz.bf16).
// 8 warps/block, 4 edges/warp, grid=3125.
// smem: Wp 8KB + KBS 16KB + XS 32KB + MB 32KB = 88KB, 2 blocks/SM.
// =========================================================
__global__ void __launch_bounds__(256, 2) k_edge(
    const float* __restrict__ x,
    const float* __restrict__ kb,
    const int*   __restrict__ ei)
{
    extern __shared__ float sme[];
    unsigned* Wp      = (unsigned*)sme;             // 2048 u32  (8KB)
    unsigned* KBS_all = Wp + 2048;                  // 4096 u32  (16KB) bf16 tiles
    float*    XS_all  = (float*)(KBS_all + 4096);   // 8 x 1024 f32 (32KB)
    __nv_bfloat162* MB_all = (__nv_bfloat162*)(XS_all + 8192); // 8 x 2 x 512 bf162 (32KB)

    const int tid  = threadIdx.x;
    const int wrp  = tid >> 5, lane = tid & 31;
    const int g    = lane >> 2, tg = lane & 3;

    for (int i = tid; i < 2048; i += 256) Wp[i] = g_kwp[i];
    __syncthreads();

    char*  KBS = (char*)(KBS_all + wrp * 512);      // 2KB bf16 tile, swizzled
    float* XS  = XS_all + wrp * 1024;               // 4KB fp32 x staging
    __nv_bfloat162* MB = MB_all + wrp * 1024;       // 2 x 2KB bf16 msg buffers

    // L2 eviction policy: kb is streamed once, keep x/x1 resident
    unsigned long long pol;
    asm volatile("createpolicy.fractional.L2::evict_first.b64 %0, 1.0;" : "=l"(pol));

    const int lrow  = lane & 15;
    const int lhalf = lane >> 4;
    const unsigned kbs_base = (unsigned)__cvta_generic_to_shared(KBS);

#pragma unroll 1
    for (int it = 0; it < 4; ++it) {
        const int e   = blockIdx.x * 32 + wrp * 4 + it;
        const int src = ei[e];
        const int dst = ei[EE + e];

        // ---- coalesced loads (kb with evict_first hint) ----
        const float4* kb4 = (const float4*)(kb + (size_t)e * TILE);
        const float4* x4  = (const float4*)(x  + (size_t)src * TILE);
        float4 kv[8], xv[8];
#pragma unroll
        for (int i = 0; i < 8; ++i)
            asm volatile("ld.global.nc.L2::cache_hint.v4.f32 {%0,%1,%2,%3}, [%4], %5;"
                         : "=f"(kv[i].x), "=f"(kv[i].y), "=f"(kv[i].z), "=f"(kv[i].w)
                         : "l"(kb4 + i * 32 + lane), "l"(pol));
#pragma unroll
        for (int i = 0; i < 8; ++i) xv[i] = x4[i * 32 + lane];

        // ---- kb -> bf16 swizzled smem ----
#pragma unroll
        for (int i = 0; i < 8; ++i) {
            const int idx = i * 32 + lane;          // float4 index in tile
            const int row = idx >> 4;               // 0..15
            const int bc  = (idx & 15) * 8;         // byte col (0..120)
            const int bcs = bc ^ ((row & 7) << 4);  // SW128 swizzle
            uint2 v;
            v.x = pk(kv[i].x, kv[i].y);
            v.y = pk(kv[i].z, kv[i].w);
            *(uint2*)(KBS + row * 128 + bcs) = v;
        }

        const int buf = it & 1;
        __nv_bfloat162* mb = MB + buf * 512;
        if (lane == 0 && it >= 2)
            asm volatile("cp.async.bulk.wait_group 1;" ::: "memory");
        __syncwarp();

        // ---- x -> fp32 staging (permuted cols) ----
#pragma unroll
        for (int i = 0; i < 8; ++i) {
            const int f    = (i * 32 + lane) * 4;   // word index
            const int row  = f >> 6;
            const int colw = f & 63;
            *(float4*)(XS + row * 64 + PERM(row, colw)) = xv[i];
        }
        __syncwarp();

        // ---- A fragments via ldmatrix ----
        unsigned A[4][4];
#pragma unroll
        for (int kt = 0; kt < 4; ++kt) {
            const int bc  = kt * 32 + lhalf * 16;
            const unsigned addr = kbs_base + lrow * 128 + (bc ^ ((lrow & 7) << 4));
            asm volatile(
                "ldmatrix.sync.aligned.m8n8.x4.shared.b16 {%0,%1,%2,%3}, [%4];"
                : "=r"(A[kt][0]), "=r"(A[kt][1]), "=r"(A[kt][2]), "=r"(A[kt][3])
                : "r"(addr));
        }

        float c[8][4];
#pragma unroll
        for (int nt = 0; nt < 8; ++nt)
            c[nt][0] = c[nt][1] = c[nt][2] = c[nt][3] = 0.f;
#pragma unroll
        for (int kt = 0; kt < 4; ++kt)
#pragma unroll
            for (int nt = 0; nt < 8; ++nt) {
                uint2 b = *(const uint2*)&Wp[((kt * 8 + nt) * 32 + lane) * 2];
                mma_bf16(c[nt], A[kt], b.x, b.y);
            }

        // ---- msg = x * k -> bf16 scatter buffer ----
#pragma unroll
        for (int nt = 0; nt < 8; ++nt) {
            const int c0 = nt * 8 + 2 * tg;
            const int pc = PERM(g, c0);             // same for rows g and g+8
            float2 a0 = *(float2*)(XS + g * 64 + pc);
            float2 a1 = *(float2*)(XS + (g + 8) * 64 + pc);
            mb[g * 32 + (pc >> 1)] =
                __floats2bfloat162_rn(a0.x * c[nt][0], a0.y * c[nt][1]);
            mb[(g + 8) * 32 + (pc >> 1)] =
                __floats2bfloat162_rn(a1.x * c[nt][2], a1.y * c[nt][3]);
        }
        __syncwarp();

        if (lane == 0) {
            asm volatile("fence.proxy.async.shared::cta;" ::: "memory");
            unsigned saddr = (unsigned)__cvta_generic_to_shared(mb);
            char* gptr = (char*)g_x1 + (size_t)dst * 2048;
            asm volatile(
                "cp.reduce.async.bulk.global.shared::cta.bulk_group.add.noftz.bf16 [%0], [%1], %2;"
                :: "l"(gptr), "r"(saddr), "r"(2048) : "memory");
            asm volatile("cp.async.bulk.commit_group;" ::: "memory");
        }
    }
    if (lane == 0)
        asm volatile("cp.async.bulk.wait_group 0;" ::: "memory");
    __syncwarp();
}

// =========================================================
// K3: persistent fused fiber conv + LN + bf16-MMA MLP + residual
// grid=148, 512 threads. Weights loaded once; fk in registers.
// Loop over groups of 8 nodes (1250 groups total), 2 warps/node MLP.
// =========================================================
#define X2S 68                                 // x2 row stride (float4-aligned)
#define FUSE_SMEM_FLOATS (8192*3 + 128*X2S + 128 + 128 + 256 + 64*5 + 16896)
#define FUSE_SMEM_BYTES  (FUSE_SMEM_FLOATS * 4)

__global__ void __launch_bounds__(512, 1) k_fuse(
    const float* __restrict__ x,
    const float* __restrict__ cb,
    const float* __restrict__ lns,
    const float* __restrict__ lnb,
    const float* __restrict__ b1,
    const float* __restrict__ b2,
    const float* __restrict__ ls,
    float*       __restrict__ out)
{
    extern __shared__ float sm[];
    unsigned* w1p  = (unsigned*)sm;                    // 8192 u32 (32KB)
    unsigned* w2p  = w1p + 8192;                       // 8192 u32 (32KB)
    unsigned* fkp  = w2p + 8192;                       // 8192 u32 = bf162 (32KB)
    float* x2    = (float*)(fkp + 8192);               // 128 x 68 f32 (34.8KB)
    float* mu_s  = x2 + 128 * X2S;                     // 128
    float* rs_s  = mu_s + 128;                         // 128
    float* b1_s  = rs_s + 128;                         // 256
    float* b2_s  = b1_s + 256;                         // 64
    float* ls_s  = b2_s + 64;                          // 64
    float* lns_s = ls_s + 64;                          // 64
    float* lnb_s = lns_s + 64;                         // 64
    float* cb_s  = lnb_s + 64;                         // 64
    unsigned* h1 = (unsigned*)(cb_s + 64);             // 128 x 132 u32 (66KB)
    __nv_bfloat16* stageh = (__nv_bfloat16*)h1;        // alias: 8 x 1024 bf16 staging

    const int tid  = threadIdx.x;
    const int wrp  = tid >> 5, lane = tid & 31;
    const int g    = lane >> 2, tg = lane & 3;
    const int nloc = wrp >> 1;        // 0..7: node within group
    const int sub  = wrp & 1;         // warp's half of the MLP

    for (int i = tid; i < 8192; i += 512) {
        w1p[i] = g_w1p[i];
        w2p[i] = g_w2p[i];
        fkp[i] = ((const unsigned*)g_fkb)[i];
    }
    if (tid < 64) {
        b2_s[tid]  = b2[tid];
        ls_s[tid]  = ls[tid] * 1e-6f;   // fold LS_VAL
        lns_s[tid] = lns[tid];
        lnb_s[tid] = lnb[tid];
        cb_s[tid]  = cb[tid];
    }
    if (tid < 256) b1_s[tid] = b1[tid];
    __syncthreads();

    // ---- hoist fiber kernel into registers: thread = (c4, p, half) ----
    const int c4 = tid & 15, fp_ = (tid >> 4) & 15, half = tid >> 8;
    __nv_bfloat162 fkr0[16], fkr1[16];
#pragma unroll
    for (int o = 0; o < 16; ++o) {
        uint2 v = *(const uint2*)&fkp[fp_ * 512 + o * 32 + 2 * c4];
        fkr0[o] = *reinterpret_cast<__nv_bfloat162*>(&v.x);
        fkr1[o] = *reinterpret_cast<__nv_bfloat162*>(&v.y);
    }
    const float4 cbv = *(const float4*)&cb_s[4 * c4];

#pragma unroll 1
    for (int grp = blockIdx.x; grp < NN / 8; grp += 148) {
        const int nodebase = grp * 8;

        // ---- stage x1 of 8 nodes (bf16, 16KB, coalesced) ----
        {
            const uint4* s4 = (const uint4*)((const char*)g_x1 + (size_t)nodebase * 2048);
            uint4* d4 = (uint4*)stageh;
#pragma unroll
            for (int i = 0; i < 2; ++i) d4[tid + i * 512] = s4[tid + i * 512];
        }
        __syncthreads();

        // ---- fiber conv (bf162 hfma2, fk in regs): 4 nodes per thread ----
#pragma unroll
        for (int n = 0; n < 4; ++n) {
            const int node = half * 4 + n;
            const __nv_bfloat16* sp = stageh + node * 1024;
            __nv_bfloat162 acc0 = __floats2bfloat162_rn(0.f, 0.f);
            __nv_bfloat162 acc1 = acc0;
#pragma unroll
            for (int o = 0; o < 16; ++o) {
                uint2 xv = *(const uint2*)(sp + o * 64 + PERM(o, 4 * c4));
                acc0 = __hfma2(*reinterpret_cast<__nv_bfloat162*>(&xv.x), fkr0[o], acc0);
                acc1 = __hfma2(*reinterpret_cast<__nv_bfloat162*>(&xv.y), fkr1[o], acc1);
            }
            float2 a0 = __bfloat1622float2(acc0);
            float2 a1 = __bfloat1622float2(acc1);
            *(float4*)&x2[(node * 16 + fp_) * X2S + 4 * c4] =
                make_float4(a0.x + cbv.x, a0.y + cbv.y, a1.x + cbv.z, a1.y + cbv.w);
        }
        __syncthreads();

        // ---- LayerNorm stats: 4 threads per row (float4, aligned via X2S=68) ----
        {
            const int row = tid >> 2, q = tid & 3;
            const float* xr = x2 + row * X2S + q * 16;
            float s = 0.f, ss = 0.f;
#pragma unroll
            for (int j = 0; j < 4; ++j) {
                float4 v = *(const float4*)(xr + j * 4);
                s  += v.x + v.y + v.z + v.w;
                ss += v.x * v.x + v.y * v.y + v.z * v.z + v.w * v.w;
            }
            s  += __shfl_xor_sync(0xffffffffu, s, 1);
            ss += __shfl_xor_sync(0xffffffffu, ss, 1);
            s  += __shfl_xor_sync(0xffffffffu, s, 2);
            ss += __shfl_xor_sync(0xffffffffu, ss, 2);
            if (q == 0) {
                const float mu  = s * (1.f / 64.f);
                const float var = ss * (1.f / 64.f) - mu * mu;
                mu_s[row] = mu;
                rs_s[row] = rsqrtf(var + 1e-6f);
            }
        }
        __syncthreads();

        // ---- build normalized A fragments ----
        const int r0  = nloc * 16 + g;
        const float mu0 = mu_s[r0],     rs0 = rs_s[r0];
        const float mu1 = mu_s[r0 + 8], rs1 = rs_s[r0 + 8];
        unsigned A[4][4];
#pragma unroll
        for (int kt = 0; kt < 4; ++kt) {
            const int k0 = kt * 16 + 2 * tg;
            float2 sc0 = *(float2*)(lns_s + k0),     bi0 = *(float2*)(lnb_s + k0);
            float2 sc1 = *(float2*)(lns_s + k0 + 8), bi1 = *(float2*)(lnb_s + k0 + 8);
            float2 v;
            v = *(float2*)(x2 + r0 * X2S + k0);
            A[kt][0] = pk((v.x - mu0) * rs0 * sc0.x + bi0.x, (v.y - mu0) * rs0 * sc0.y + bi0.y);
            v = *(float2*)(x2 + (r0 + 8) * X2S + k0);
            A[kt][1] = pk((v.x - mu1) * rs1 * sc0.x + bi0.x, (v.y - mu1) * rs1 * sc0.y + bi0.y);
            v = *(float2*)(x2 + r0 * X2S + k0 + 8);
            A[kt][2] = pk((v.x - mu0) * rs0 * sc1.x + bi1.x, (v.y - mu0) * rs0 * sc1.y + bi1.y);
            v = *(float2*)(x2 + (r0 + 8) * X2S + k0 + 8);
            A[kt][3] = pk((v.x - mu1) * rs1 * sc1.x + bi1.x, (v.y - mu1) * rs1 * sc1.y + bi1.y);
        }

        // ---- MLP1: this warp's half (16 of 32 n-tiles) ----
        {
            float c1r[16][4];
#pragma unroll
            for (int nt = 0; nt < 16; ++nt) {
                const int col = (sub * 16 + nt) * 8 + 2 * tg;
                c1r[nt][0] = b1_s[col]; c1r[nt][1] = b1_s[col + 1];
                c1r[nt][2] = b1_s[col]; c1r[nt][3] = b1_s[col + 1];
            }
#pragma unroll
            for (int kt = 0; kt < 4; ++kt)
#pragma unroll
                for (int nt = 0; nt < 16; ++nt) {
                    const int ntg = sub * 16 + nt;
                    uint2 b = *(const uint2*)&w1p[((kt * 32 + ntg) * 32 + lane) * 2];
                    mma_bf16(c1r[nt], A[kt], b.x, b.y);
                }
#pragma unroll
            for (int nt = 0; nt < 16; ++nt) {
                const int ntg = sub * 16 + nt;
                const float p0 = fmaxf(c1r[nt][0], 0.f), p1 = fmaxf(c1r[nt][1], 0.f);
                const float p2 = fmaxf(c1r[nt][2], 0.f), p3 = fmaxf(c1r[nt][3], 0.f);
                h1[r0 * 132 + ntg * 4 + tg]       = pk(p0, p1);
                h1[(r0 + 8) * 132 + ntg * 4 + tg] = pk(p2, p3);
            }
        }
        __syncthreads();   // h1 complete across each node's warp pair

        // ---- MLP2: this warp's quarter (4 of 8 n-tiles) ----
        float d[4][4];
#pragma unroll
        for (int nt = 0; nt < 4; ++nt) {
            const int col = (sub * 4 + nt) * 8 + 2 * tg;
            d[nt][0] = b2_s[col]; d[nt][1] = b2_s[col + 1];
            d[nt][2] = b2_s[col]; d[nt][3] = b2_s[col + 1];
        }
#pragma unroll
        for (int kt = 0; kt < 16; ++kt) {
            unsigned a[4];
            a[0] = h1[r0 * 132 + kt * 8 + tg];
            a[1] = h1[(r0 + 8) * 132 + kt * 8 + tg];
            a[2] = h1[r0 * 132 + kt * 8 + 4 + tg];
            a[3] = h1[(r0 + 8) * 132 + kt * 8 + 4 + tg];
#pragma unroll
            for (int nt = 0; nt < 4; ++nt) {
                uint2 b = *(const uint2*)&w2p[((kt * 8 + sub * 4 + nt) * 32 + lane) * 2];
                mma_bf16(d[nt], a, b.x, b.y);
            }
        }

        // ---- epilogue: out = ls * d + x ----
        {
            const int node = nodebase + nloc;
            const float* xres = x + (size_t)node * TILE;
            float* op = out + (size_t)node * TILE;
#pragma unroll
            for (int nt = 0; nt < 4; ++nt) {
                const int col = (sub * 4 + nt) * 8 + 2 * tg;
                float2 xv0 = *(const float2*)(xres + g * 64 + col);
                float2 xv1 = *(const float2*)(xres + (g + 8) * 64 + col);
                *(float2*)(op + g * 64 + col) =
                    make_float2(ls_s[col] * d[nt][0] + xv0.x, ls_s[col + 1] * d[nt][1] + xv0.y);
                *(float2*)(op + (g + 8) * 64 + col) =
                    make_float2(ls_s[col] * d[nt][2] + xv1.x, ls_s[col + 1] * d[nt][3] + xv1.y);
            }
        }
        __syncthreads();   // protect x2/h1/stage for next group
    }
}

// =========================================================
extern "C" void kernel_launch(void* const* d_in, const int* in_sizes, int n_in,
                              void* d_out, int out_size)
{
    (void)in_sizes; (void)n_in; (void)out_size;
    const float* x   = (const float*)d_in[0];
    const float* kb  = (const float*)d_in[1];
    const float* fkb = (const float*)d_in[2];
    const int*   ei  = (const int*)  d_in[3];
    const float* kw  = (const float*)d_in[4];
    const float* fkw = (const float*)d_in[5];
    const float* cb  = (const float*)d_in[6];
    const float* lns = (const float*)d_in[7];
    const float* lnb = (const float*)d_in[8];
    const float* w1  = (const float*)d_in[9];
    const float* b1  = (const float*)d_in[10];
    const float* w2  = (const float*)d_in[11];
    const float* b2  = (const float*)d_in[12];
    const float* ls  = (const float*)d_in[13];
    float* out = (float*)d_out;

    const int edge_smem = 90112;   // 88KB: Wp 8K + KBS 16K + XS 32K + MB 32K
    cudaFuncSetAttribute(k_edge, cudaFuncAttributeMaxDynamicSharedMemorySize, edge_smem);
    cudaFuncSetAttribute(k_fuse, cudaFuncAttributeMaxDynamicSharedMemorySize, FUSE_SMEM_BYTES);

    k_zero<<<2560, 256>>>();
    k_fk<<<OO * OO, 32>>>(fkb, fkw);
    k_pack<<<1, 256>>>(kw, w1, w2);
    k_edge<<<EE / 32, 256, edge_smem>>>(x, kb, ei);
    k_fuse<<<148, 512, FUSE_SMEM_BYTES>>>(x, cb, lns, lnb, b1, b2, ls, out);
}

// round 12
// speedup vs baseline: 6.8746x; 1.0411x over previous
#include <cuda_runtime.h>
#include <cuda_bf16.h>

#define NN   10000
#define OO   16
#define CC   64
#define EE   100000
#define KDD  64
#define NOC  (NN*OO*CC)          // 10,240,000
#define TILE (OO*CC)             // 1024 elements per node/edge tile
#define NGRP (NN/8)              // 1250 groups of 8 nodes

// column permutation applied to g_x1 / g_xb tiles (element index within a 64-elem row)
#define PERM(row, col) ((col) ^ (((row) & 3) << 3))

// -------- device scratch (no allocations allowed) --------
__device__ __align__(16) __nv_bfloat16  g_x1[NOC];      // 20.5 MB spatial-conv accumulator (bf16, PERMuted)
__device__ __align__(16) __nv_bfloat16  g_xb[NOC];      // 20.5 MB bf16 permuted copy of x
__device__ __align__(16) __nv_bfloat162 g_fkb[8192];    // fiber kernel bf16 (pre /O)
__device__ __align__(16) unsigned       g_kwp[2048];    // kernel_w  B-frags (4kt x 8nt)
__device__ __align__(16) unsigned       g_w1p[8192];    // w1 B-frags (4kt x 32nt)
__device__ __align__(16) unsigned       g_w2p[8192];    // w2 B-frags (16kt x 8nt)

// -------- helpers --------
__device__ __forceinline__ unsigned pk(float lo, float hi) {
    __nv_bfloat162 t = __floats2bfloat162_rn(lo, hi);   // .x = lo (low 16 bits)
    return *reinterpret_cast<unsigned*>(&t);
}

__device__ __forceinline__ void mma_bf16(float* c, const unsigned* a, unsigned b0, unsigned b1) {
    asm volatile(
        "mma.sync.aligned.m16n8k16.row.col.f32.bf16.bf16.f32 "
        "{%0,%1,%2,%3}, {%4,%5,%6,%7}, {%8,%9}, {%0,%1,%2,%3};"
        : "+f"(c[0]), "+f"(c[1]), "+f"(c[2]), "+f"(c[3])
        : "r"(a[0]), "r"(a[1]), "r"(a[2]), "r"(a[3]), "r"(b0), "r"(b1));
}

__device__ __forceinline__ void mbar_wait(unsigned mbar, int phase) {
    asm volatile(
        "{\n\t.reg .pred P1;\n\t"
        "WAIT_LOOP_%=:\n\t"
        "mbarrier.try_wait.parity.acquire.cta.shared::cta.b64 P1, [%0], %1, 0x989680;\n\t"
        "@P1 bra.uni WAIT_DONE_%=;\n\t"
        "bra.uni WAIT_LOOP_%=;\n\t"
        "WAIT_DONE_%=:\n\t}"
        :: "r"(mbar), "r"(phase) : "memory");
}

// =========================================================
// K0: zero the bf16 x1 accumulator (20.5 MB)
// =========================================================
__global__ void k_zero() {
    uint4* p = reinterpret_cast<uint4*>(g_x1);
    const int n16 = NOC * 2 / 16;    // 1,280,000
    int i = blockIdx.x * blockDim.x + threadIdx.x;
    const int stride = gridDim.x * blockDim.x;
    const uint4 z = make_uint4(0u, 0u, 0u, 0u);
    for (; i < n16; i += stride) p[i] = z;
}

// =========================================================
// K0b: x (fp32) -> g_xb (bf16, permuted tile layout)
// =========================================================
__global__ void k_xprep(const float* __restrict__ x) {
    const int n4 = NOC / 4;          // 2,560,000 float4s
    int i = blockIdx.x * blockDim.x + threadIdx.x;
    const int stride = gridDim.x * blockDim.x;
    for (; i < n4; i += stride) {
        float4 v = ((const float4*)x)[i];
        const int node = i >> 8;
        const int f    = (i & 255) * 4;      // element index within tile
        const int row  = f >> 6, col = f & 63;
        const int pc   = PERM(row, col);
        uint2 o;
        o.x = pk(v.x, v.y);
        o.y = pk(v.z, v.w);
        *(uint2*)(g_xb + (size_t)node * 1024 + row * 64 + pc) = o;
    }
}

// =========================================================
// K1: fk[p][o][c] = (1/O) * sum_kd FKB[p,o,kd] * FW[kd,c]  -> bf16 pairs
// =========================================================
__global__ void k_fk(const float* __restrict__ fkb, const float* __restrict__ fw) {
    __shared__ float s[KDD];
    const int po = blockIdx.x;
    const int t  = threadIdx.x;
    s[t]      = fkb[po * KDD + t];
    s[t + 32] = fkb[po * KDD + t + 32];
    __syncthreads();
    float a0 = 0.f, a1 = 0.f;
#pragma unroll 16
    for (int kd = 0; kd < KDD; kd++) {
        a0 += s[kd] * fw[kd * CC + 2 * t];
        a1 += s[kd] * fw[kd * CC + 2 * t + 1];
    }
    g_fkb[po * 32 + t] = __floats2bfloat162_rn(a0 * (1.0f / OO), a1 * (1.0f / OO));
}

// =========================================================
// K1b: pack kernel_w / w1 / w2 into mma B-fragment layout (bf16)
// =========================================================
__global__ void k_pack(const float* __restrict__ kw,
                       const float* __restrict__ w1,
                       const float* __restrict__ w2) {
    const int tid  = threadIdx.x;
    const int wrp  = tid >> 5, lane = tid & 31;
    const int g    = lane >> 2, tg = lane & 3;
    for (int f = wrp; f < 32; f += 8) {
        const int kt = f >> 3, nt = f & 7;
        const int k = kt * 16 + 2 * tg, n = nt * 8 + g;
        g_kwp[(f * 32 + lane) * 2 + 0] = pk(kw[k * 64 + n],       kw[(k + 1) * 64 + n]);
        g_kwp[(f * 32 + lane) * 2 + 1] = pk(kw[(k + 8) * 64 + n], kw[(k + 9) * 64 + n]);
    }
    for (int f = wrp; f < 128; f += 8) {
        const int kt = f >> 5, nt = f & 31;
        const int k = kt * 16 + 2 * tg, n = nt * 8 + g;
        g_w1p[(f * 32 + lane) * 2 + 0] = pk(w1[k * 256 + n],       w1[(k + 1) * 256 + n]);
        g_w1p[(f * 32 + lane) * 2 + 1] = pk(w1[(k + 8) * 256 + n], w1[(k + 9) * 256 + n]);
    }
    for (int f = wrp; f < 128; f += 8) {
        const int kt = f >> 3, nt = f & 7;
        const int k = kt * 16 + 2 * tg, n = nt * 8 + g;
        g_w2p[(f * 32 + lane) * 2 + 0] = pk(w2[k * 64 + n],       w2[(k + 1) * 64 + n]);
        g_w2p[(f * 32 + lane) * 2 + 1] = pk(w2[(k + 8) * 64 + n], w2[(k + 9) * 64 + n]);
    }
}

// =========================================================
// K2: edge conv. kb streamed with L2::evict_first; x from bf16 g_xb;
// msg built in-place in a double-buffered bf16 scatter buffer.
// 8 warps/block, 4 edges/warp, grid=3125.
// smem: Wp 8KB + KBS 16KB + XB 32KB = 56KB, 2 blocks/SM.
// =========================================================
__global__ void __launch_bounds__(256, 2) k_edge(
    const float* __restrict__ kb,
    const int*   __restrict__ ei)
{
    extern __shared__ float sme[];
    unsigned* Wp      = (unsigned*)sme;             // 2048 u32  (8KB)
    unsigned* KBS_all = Wp + 2048;                  // 4096 u32  (16KB) bf16 kb tiles
    unsigned* XB_all  = KBS_all + 4096;             // 8 warps x 2 x 512 u32 (32KB)

    const int tid  = threadIdx.x;
    const int wrp  = tid >> 5, lane = tid & 31;
    const int g    = lane >> 2, tg = lane & 3;

    for (int i = tid; i < 2048; i += 256) Wp[i] = g_kwp[i];
    __syncthreads();

    char*     KBS = (char*)(KBS_all + wrp * 512);   // 2KB bf16 tile, swizzled
    unsigned* XB  = XB_all + wrp * 1024;            // 2 x 2KB bf16 msg buffers

    // L2 eviction policy: kb is streamed once, keep xb/x1 resident
    unsigned long long pol;
    asm volatile("createpolicy.fractional.L2::evict_first.b64 %0, 1.0;" : "=l"(pol));

    const int lrow  = lane & 15;
    const int lhalf = lane >> 4;
    const unsigned kbs_base = (unsigned)__cvta_generic_to_shared(KBS);

#pragma unroll 1
    for (int it = 0; it < 4; ++it) {
        const int e   = blockIdx.x * 32 + wrp * 4 + it;
        const int src = ei[e];
        const int dst = ei[EE + e];

        // ---- coalesced loads: kb fp32 (evict_first) + xb bf16 ----
        const float4* kb4 = (const float4*)(kb + (size_t)e * TILE);
        const uint4*  xb4 = (const uint4*)(g_xb + (size_t)src * TILE);
        float4 kv[8];
        uint4  xv[4];
#pragma unroll
        for (int i = 0; i < 8; ++i)
            asm volatile("ld.global.nc.L2::cache_hint.v4.f32 {%0,%1,%2,%3}, [%4], %5;"
                         : "=f"(kv[i].x), "=f"(kv[i].y), "=f"(kv[i].z), "=f"(kv[i].w)
                         : "l"(kb4 + i * 32 + lane), "l"(pol));
#pragma unroll
        for (int i = 0; i < 4; ++i) xv[i] = xb4[i * 32 + lane];

        // ---- kb -> bf16 swizzled smem ----
#pragma unroll
        for (int i = 0; i < 8; ++i) {
            const int idx = i * 32 + lane;          // float4 index in tile
            const int row = idx >> 4;               // 0..15
            const int bc  = (idx & 15) * 8;         // byte col (0..120)
            const int bcs = bc ^ ((row & 7) << 4);  // SW128 swizzle
            uint2 v;
            v.x = pk(kv[i].x, kv[i].y);
            v.y = pk(kv[i].z, kv[i].w);
            *(uint2*)(KBS + row * 128 + bcs) = v;
        }

        const int buf = it & 1;
        unsigned* mb = XB + buf * 512;
        if (lane == 0 && it >= 2)
            asm volatile("cp.async.bulk.wait_group 1;" ::: "memory");
        __syncwarp();   // scatter of this buffer drained; KBS stores visible

        // ---- stage xb (already permuted) into msg buffer ----
#pragma unroll
        for (int i = 0; i < 4; ++i)
            ((uint4*)mb)[i * 32 + lane] = xv[i];
        __syncwarp();

        // ---- A fragments via ldmatrix ----
        unsigned A[4][4];
#pragma unroll
        for (int kt = 0; kt < 4; ++kt) {
            const int bc  = kt * 32 + lhalf * 16;
            const unsigned addr = kbs_base + lrow * 128 + (bc ^ ((lrow & 7) << 4));
            asm volatile(
                "ldmatrix.sync.aligned.m8n8.x4.shared.b16 {%0,%1,%2,%3}, [%4];"
                : "=r"(A[kt][0]), "=r"(A[kt][1]), "=r"(A[kt][2]), "=r"(A[kt][3])
                : "r"(addr));
        }

        float c[8][4];
#pragma unroll
        for (int nt = 0; nt < 8; ++nt)
            c[nt][0] = c[nt][1] = c[nt][2] = c[nt][3] = 0.f;
#pragma unroll
        for (int kt = 0; kt < 4; ++kt)
#pragma unroll
            for (int nt = 0; nt < 8; ++nt) {
                uint2 b = *(const uint2*)&Wp[((kt * 8 + nt) * 32 + lane) * 2];
                mma_bf16(c[nt], A[kt], b.x, b.y);
            }

        // ---- msg = x * k, in place (bf16 hmul2) ----
#pragma unroll
        for (int nt = 0; nt < 8; ++nt) {
            const int c0 = nt * 8 + 2 * tg;
            const int w  = PERM(g, c0) >> 1;        // bf162 word col (same for g, g+8)
            unsigned x0 = mb[g * 32 + w];
            unsigned x1 = mb[(g + 8) * 32 + w];
            unsigned k0 = pk(c[nt][0], c[nt][1]);
            unsigned k1 = pk(c[nt][2], c[nt][3]);
            __nv_bfloat162 m0 = __hmul2(*(__nv_bfloat162*)&x0, *(__nv_bfloat162*)&k0);
            __nv_bfloat162 m1 = __hmul2(*(__nv_bfloat162*)&x1, *(__nv_bfloat162*)&k1);
            mb[g * 32 + w]       = *(unsigned*)&m0;
            mb[(g + 8) * 32 + w] = *(unsigned*)&m1;
        }
        __syncwarp();

        if (lane == 0) {
            asm volatile("fence.proxy.async.shared::cta;" ::: "memory");
            unsigned saddr = (unsigned)__cvta_generic_to_shared(mb);
            char* gptr = (char*)g_x1 + (size_t)dst * 2048;
            asm volatile(
                "cp.reduce.async.bulk.global.shared::cta.bulk_group.add.noftz.bf16 [%0], [%1], %2;"
                :: "l"(gptr), "r"(saddr), "r"(2048) : "memory");
            asm volatile("cp.async.bulk.commit_group;" ::: "memory");
        }
    }
    if (lane == 0)
        asm volatile("cp.async.bulk.wait_group 0;" ::: "memory");
    __syncwarp();
}

// =========================================================
// K3: persistent fused fiber conv + LN + bf16-MMA MLP + residual
// grid=148, 512 threads. x1 tiles prefetched via cp.async.bulk (double buffer),
// fk in registers from global, per-node-pair named barrier between MLP1/MLP2.
// =========================================================
#define X2S 68                                 // x2 row stride (float4-aligned)
#define FUSE_SMEM_FLOATS (8192*2 + 128*X2S + 128 + 128 + 256 + 64*5 + 4 + 16896 + 8192)
#define FUSE_SMEM_BYTES  (FUSE_SMEM_FLOATS * 4)

__global__ void __launch_bounds__(512, 1) k_fuse(
    const float* __restrict__ x,
    const float* __restrict__ cb,
    const float* __restrict__ lns,
    const float* __restrict__ lnb,
    const float* __restrict__ b1,
    const float* __restrict__ b2,
    const float* __restrict__ ls,
    float*       __restrict__ out)
{
    extern __shared__ float sm[];
    unsigned* w1p  = (unsigned*)sm;                    // 8192 u32 (32KB)
    unsigned* w2p  = w1p + 8192;                       // 8192 u32 (32KB)
    float* x2    = (float*)(w2p + 8192);               // 128 x 68 f32 (34.8KB)
    float* mu_s  = x2 + 128 * X2S;                     // 128
    float* rs_s  = mu_s + 128;                         // 128
    float* b1_s  = rs_s + 128;                         // 256
    float* b2_s  = b1_s + 256;                         // 64
    float* ls_s  = b2_s + 64;                          // 64
    float* lns_s = ls_s + 64;                          // 64
    float* lnb_s = lns_s + 64;                         // 64
    float* cb_s  = lnb_s + 64;                         // 64
    unsigned long long* mbar = (unsigned long long*)(cb_s + 64);  // 2 mbarriers (16B)
    unsigned* h1 = (unsigned*)(mbar + 2);              // 128 x 132 u32 (66KB)
    __nv_bfloat16* stage = (__nv_bfloat16*)(h1 + 16896); // 2 x 8192 bf16 (32KB)

    const int tid  = threadIdx.x;
    const int wrp  = tid >> 5, lane = tid & 31;
    const int g    = lane >> 2, tg = lane & 3;
    const int nloc = wrp >> 1;        // 0..7: node within group
    const int sub  = wrp & 1;         // warp's half of the MLP

    const unsigned mb0 = (unsigned)__cvta_generic_to_shared(&mbar[0]);
    const unsigned mb1 = (unsigned)__cvta_generic_to_shared(&mbar[1]);

    for (int i = tid; i < 8192; i += 512) {
        w1p[i] = g_w1p[i];
        w2p[i] = g_w2p[i];
    }
    if (tid < 64) {
        b2_s[tid]  = b2[tid];
        ls_s[tid]  = ls[tid] * 1e-6f;   // fold LS_VAL
        lns_s[tid] = lns[tid];
        lnb_s[tid] = lnb[tid];
        cb_s[tid]  = cb[tid];
    }
    if (tid < 256) b1_s[tid] = b1[tid];
    if (tid == 0) {
        asm volatile("mbarrier.init.shared.b64 [%0], 1;" :: "r"(mb0) : "memory");
        asm volatile("mbarrier.init.shared.b64 [%0], 1;" :: "r"(mb1) : "memory");
    }

    // ---- hoist fiber kernel into registers: thread = (c4, p, half) ----
    const int c4 = tid & 15, fp_ = (tid >> 4) & 15, half = tid >> 8;
    __nv_bfloat162 fkr0[16], fkr1[16];
#pragma unroll
    for (int o = 0; o < 16; ++o) {
        uint2 v = *(const uint2*)&((const unsigned*)g_fkb)[fp_ * 512 + o * 32 + 2 * c4];
        fkr0[o] = *reinterpret_cast<__nv_bfloat162*>(&v.x);
        fkr1[o] = *reinterpret_cast<__nv_bfloat162*>(&v.y);
    }
    __syncthreads();
    const float4 cbv = *(const float4*)&cb_s[4 * c4];

    // ---- prologue: prefetch first group's x1 tile into stage buf 0 ----
    if (tid == 0) {
        asm volatile("mbarrier.arrive.expect_tx.shared.b64 _, [%0], 16384;" :: "r"(mb0) : "memory");
        unsigned sdst = (unsigned)__cvta_generic_to_shared(stage);
        const char* gsrc = (const char*)g_x1 + (size_t)blockIdx.x * 16384;
        asm volatile(
            "cp.async.bulk.shared::cta.global.mbarrier::complete_tx::bytes [%0], [%1], 16384, [%2];"
            :: "r"(sdst), "l"(gsrc), "r"(mb0) : "memory");
    }

    int ph0 = 0, ph1 = 0;
    int it = 0;
#pragma unroll 1
    for (int grp = blockIdx.x; grp < NGRP; grp += 148, ++it) {
        const int nodebase = grp * 8;
        const int buf = it & 1;
        const __nv_bfloat16* stg = stage + buf * 8192;

        // ---- wait for this group's x1 tile ----
        if (buf == 0) { mbar_wait(mb0, ph0); ph0 ^= 1; }
        else          { mbar_wait(mb1, ph1); ph1 ^= 1; }

        // ---- fiber conv (bf162 hfma2, fk in regs): 4 nodes per thread ----
#pragma unroll
        for (int n = 0; n < 4; ++n) {
            const int node = half * 4 + n;
            const __nv_bfloat16* sp = stg + node * 1024;
            __nv_bfloat162 acc0 = __floats2bfloat162_rn(0.f, 0.f);
            __nv_bfloat162 acc1 = acc0;
#pragma unroll
            for (int o = 0; o < 16; ++o) {
                uint2 xv = *(const uint2*)(sp + o * 64 + PERM(o, 4 * c4));
                acc0 = __hfma2(*reinterpret_cast<__nv_bfloat162*>(&xv.x), fkr0[o], acc0);
                acc1 = __hfma2(*reinterpret_cast<__nv_bfloat162*>(&xv.y), fkr1[o], acc1);
            }
            float2 a0 = __bfloat1622float2(acc0);
            float2 a1 = __bfloat1622float2(acc1);
            *(float4*)&x2[(node * 16 + fp_) * X2S + 4 * c4] =
                make_float4(a0.x + cbv.x, a0.y + cbv.y, a1.x + cbv.z, a1.y + cbv.w);
        }
        __syncthreads();   // x2 ready; everyone done reading stage[buf]

        // ---- prefetch next group's x1 into the other buffer ----
        if (tid == 0 && grp + 148 < NGRP) {
            const unsigned mbn = (buf == 0) ? mb1 : mb0;
            asm volatile("mbarrier.arrive.expect_tx.shared.b64 _, [%0], 16384;" :: "r"(mbn) : "memory");
            unsigned sdst = (unsigned)__cvta_generic_to_shared(stage + (buf ^ 1) * 8192);
            const char* gsrc = (const char*)g_x1 + (size_t)(grp + 148) * 16384;
            asm volatile(
                "cp.async.bulk.shared::cta.global.mbarrier::complete_tx::bytes [%0], [%1], 16384, [%2];"
                :: "r"(sdst), "l"(gsrc), "r"(mbn) : "memory");
        }

        // ---- LayerNorm stats: 4 threads per row (float4, aligned via X2S=68) ----
        {
            const int row = tid >> 2, q = tid & 3;
            const float* xr = x2 + row * X2S + q * 16;
            float s = 0.f, ss = 0.f;
#pragma unroll
            for (int j = 0; j < 4; ++j) {
                float4 v = *(const float4*)(xr + j * 4);
                s  += v.x + v.y + v.z + v.w;
                ss += v.x * v.x + v.y * v.y + v.z * v.z + v.w * v.w;
            }
            s  += __shfl_xor_sync(0xffffffffu, s, 1);
            ss += __shfl_xor_sync(0xffffffffu, ss, 1);
            s  += __shfl_xor_sync(0xffffffffu, s, 2);
            ss += __shfl_xor_sync(0xffffffffu, ss, 2);
            if (q == 0) {
                const float mu  = s * (1.f / 64.f);
                const float var = ss * (1.f / 64.f) - mu * mu;
                mu_s[row] = mu;
                rs_s[row] = rsqrtf(var + 1e-6f);
            }
        }
        __syncthreads();

        // ---- build normalized A fragments ----
        const int r0  = nloc * 16 + g;
        const float mu0 = mu_s[r0],     rs0 = rs_s[r0];
        const float mu1 = mu_s[r0 + 8], rs1 = rs_s[r0 + 8];
        unsigned A[4][4];
#pragma unroll
        for (int kt = 0; kt < 4; ++kt) {
            const int k0 = kt * 16 + 2 * tg;
            float2 sc0 = *(float2*)(lns_s + k0),     bi0 = *(float2*)(lnb_s + k0);
            float2 sc1 = *(float2*)(lns_s + k0 + 8), bi1 = *(float2*)(lnb_s + k0 + 8);
            float2 v;
            v = *(float2*)(x2 + r0 * X2S + k0);
            A[kt][0] = pk((v.x - mu0) * rs0 * sc0.x + bi0.x, (v.y - mu0) * rs0 * sc0.y + bi0.y);
            v = *(float2*)(x2 + (r0 + 8) * X2S + k0);
            A[kt][1] = pk((v.x - mu1) * rs1 * sc0.x + bi0.x, (v.y - mu1) * rs1 * sc0.y + bi0.y);
            v = *(float2*)(x2 + r0 * X2S + k0 + 8);
            A[kt][2] = pk((v.x - mu0) * rs0 * sc1.x + bi1.x, (v.y - mu0) * rs0 * sc1.y + bi1.y);
            v = *(float2*)(x2 + (r0 + 8) * X2S + k0 + 8);
            A[kt][3] = pk((v.x - mu1) * rs1 * sc1.x + bi1.x, (v.y - mu1) * rs1 * sc1.y + bi1.y);
        }

        // ---- MLP1: this warp's half (16 of 32 n-tiles) ----
        {
            float c1r[16][4];
#pragma unroll
            for (int nt = 0; nt < 16; ++nt) {
                const int col = (sub * 16 + nt) * 8 + 2 * tg;
                c1r[nt][0] = b1_s[col]; c1r[nt][1] = b1_s[col + 1];
                c1r[nt][2] = b1_s[col]; c1r[nt][3] = b1_s[col + 1];
            }
#pragma unroll
            for (int kt = 0; kt < 4; ++kt)
#pragma unroll
                for (int nt = 0; nt < 16; ++nt) {
                    const int ntg = sub * 16 + nt;
                    uint2 b = *(const uint2*)&w1p[((kt * 32 + ntg) * 32 + lane) * 2];
                    mma_bf16(c1r[nt], A[kt], b.x, b.y);
                }
#pragma unroll
            for (int nt = 0; nt < 16; ++nt) {
                const int ntg = sub * 16 + nt;
                const float p0 = fmaxf(c1r[nt][0], 0.f), p1 = fmaxf(c1r[nt][1], 0.f);
                const float p2 = fmaxf(c1r[nt][2], 0.f), p3 = fmaxf(c1r[nt][3], 0.f);
                h1[r0 * 132 + ntg * 4 + tg]       = pk(p0, p1);
                h1[(r0 + 8) * 132 + ntg * 4 + tg] = pk(p2, p3);
            }
        }
        // h1 is node-pair local: named barrier over the pair's 64 threads
        asm volatile("bar.sync %0, 64;" :: "r"(1 + nloc) : "memory");

        // ---- MLP2: this warp's quarter (4 of 8 n-tiles) ----
        float d[4][4];
#pragma unroll
        for (int nt = 0; nt < 4; ++nt) {
            const int col = (sub * 4 + nt) * 8 + 2 * tg;
            d[nt][0] = b2_s[col]; d[nt][1] = b2_s[col + 1];
            d[nt][2] = b2_s[col]; d[nt][3] = b2_s[col + 1];
        }
#pragma unroll
        for (int kt = 0; kt < 16; ++kt) {
            unsigned a[4];
            a[0] = h1[r0 * 132 + kt * 8 + tg];
            a[1] = h1[(r0 + 8) * 132 + kt * 8 + tg];
            a[2] = h1[r0 * 132 + kt * 8 + 4 + tg];
            a[3] = h1[(r0 + 8) * 132 + kt * 8 + 4 + tg];
#pragma unroll
            for (int nt = 0; nt < 4; ++nt) {
                uint2 b = *(const uint2*)&w2p[((kt * 8 + sub * 4 + nt) * 32 + lane) * 2];
                mma_bf16(d[nt], a, b.x, b.y);
            }
        }

        // ---- epilogue: out = ls * d + x ----
        {
            const int node = nodebase + nloc;
            const float* xres = x + (size_t)node * TILE;
            float* op = out + (size_t)node * TILE;
#pragma unroll
            for (int nt = 0; nt < 4; ++nt) {
                const int col = (sub * 4 + nt) * 8 + 2 * tg;
                float2 xv0 = *(const float2*)(xres + g * 64 + col);
                float2 xv1 = *(const float2*)(xres + (g + 8) * 64 + col);
                *(float2*)(op + g * 64 + col) =
                    make_float2(ls_s[col] * d[nt][0] + xv0.x, ls_s[col + 1] * d[nt][1] + xv0.y);
                *(float2*)(op + (g + 8) * 64 + col) =
                    make_float2(ls_s[col] * d[nt][2] + xv1.x, ls_s[col + 1] * d[nt][3] + xv1.y);
            }
        }
        __syncthreads();   // protect x2/h1 for next group
    }
}

// =========================================================
extern "C" void kernel_launch(void* const* d_in, const int* in_sizes, int n_in,
                              void* d_out, int out_size)
{
    (void)in_sizes; (void)n_in; (void)out_size;
    const float* x   = (const float*)d_in[0];
    const float* kb  = (const float*)d_in[1];
    const float* fkb = (const float*)d_in[2];
    const int*   ei  = (const int*)  d_in[3];
    const float* kw  = (const float*)d_in[4];
    const float* fkw = (const float*)d_in[5];
    const float* cb  = (const float*)d_in[6];
    const float* lns = (const float*)d_in[7];
    const float* lnb = (const float*)d_in[8];
    const float* w1  = (const float*)d_in[9];
    const float* b1  = (const float*)d_in[10];
    const float* w2  = (const float*)d_in[11];
    const float* b2  = (const float*)d_in[12];
    const float* ls  = (const float*)d_in[13];
    float* out = (float*)d_out;

    const int edge_smem = 57344;   // 56KB: Wp 8K + KBS 16K + XB 32K
    cudaFuncSetAttribute(k_edge, cudaFuncAttributeMaxDynamicSharedMemorySize, edge_smem);
    cudaFuncSetAttribute(k_fuse, cudaFuncAttributeMaxDynamicSharedMemorySize, FUSE_SMEM_BYTES);

    k_zero<<<2560, 256>>>();
    k_xprep<<<2560, 256>>>(x);
    k_fk<<<OO * OO, 32>>>(fkb, fkw);
    k_pack<<<1, 256>>>(kw, w1, w2);
    k_edge<<<EE / 32, 256, edge_smem>>>(kb, ei);
    k_fuse<<<148, 512, FUSE_SMEM_BYTES>>>(x, cb, lns, lnb, b1, b2, ls, out);
}

// round 14
// speedup vs baseline: 7.4918x; 1.0898x over previous
#include <cuda_runtime.h>
#include <cuda_bf16.h>

#define NN   10000
#define OO   16
#define CC   64
#define EE   100000
#define KDD  64
#define NOC  (NN*OO*CC)          // 10,240,000
#define TILE (OO*CC)             // 1024 elements per node/edge tile
#define NGRP (NN/8)              // 1250 groups of 8 nodes

// column permutation applied to g_x1 / g_xb tiles (element index within a 64-elem row)
#define PERM(row, col) ((col) ^ (((row) & 3) << 3))

// -------- device scratch (no allocations allowed) --------
__device__ __align__(16) __nv_bfloat16  g_x1[NOC];      // 20.5 MB spatial-conv accumulator (bf16, PERMuted)
__device__ __align__(16) __nv_bfloat16  g_xb[NOC];      // 20.5 MB bf16 permuted copy of x
__device__ __align__(16) __nv_bfloat162 g_fkb[8192];    // fiber kernel bf16 (pre /O)
__device__ __align__(16) unsigned       g_kwp[2048];    // kernel_w  B-frags (4kt x 8nt)
__device__ __align__(16) unsigned       g_w1p[8192];    // w1 B-frags (4kt x 32nt)
__device__ __align__(16) unsigned       g_w2p[8192];    // w2 B-frags (16kt x 8nt)

// -------- helpers --------
__device__ __forceinline__ unsigned pk(float lo, float hi) {
    __nv_bfloat162 t = __floats2bfloat162_rn(lo, hi);   // .x = lo (low 16 bits)
    return *reinterpret_cast<unsigned*>(&t);
}

__device__ __forceinline__ void mma_bf16(float* c, const unsigned* a, unsigned b0, unsigned b1) {
    asm volatile(
        "mma.sync.aligned.m16n8k16.row.col.f32.bf16.bf16.f32 "
        "{%0,%1,%2,%3}, {%4,%5,%6,%7}, {%8,%9}, {%0,%1,%2,%3};"
        : "+f"(c[0]), "+f"(c[1]), "+f"(c[2]), "+f"(c[3])
        : "r"(a[0]), "r"(a[1]), "r"(a[2]), "r"(a[3]), "r"(b0), "r"(b1));
}

__device__ __forceinline__ void mbar_wait(unsigned mbar, int phase) {
    asm volatile(
        "{\n\t.reg .pred P1;\n\t"
        "WAIT_LOOP_%=:\n\t"
        "mbarrier.try_wait.parity.acquire.cta.shared::cta.b64 P1, [%0], %1, 0x989680;\n\t"
        "@P1 bra.uni WAIT_DONE_%=;\n\t"
        "bra.uni WAIT_LOOP_%=;\n\t"
        "WAIT_DONE_%=:\n\t}"
        :: "r"(mbar), "r"(phase) : "memory");
}

// =========================================================
// K0: fused prep — zero g_x1 AND build g_xb (bf16 permuted x) in one pass
// =========================================================
__global__ void k_prep0(const float* __restrict__ x) {
    const int n4 = NOC / 4;          // 2,560,000 float4s
    int i = blockIdx.x * blockDim.x + threadIdx.x;
    const int stride = gridDim.x * blockDim.x;
    const uint2 z = make_uint2(0u, 0u);
    for (; i < n4; i += stride) {
        float4 v = ((const float4*)x)[i];
        const int node = i >> 8;
        const int f    = (i & 255) * 4;      // element index within tile
        const int row  = f >> 6, col = f & 63;
        const int pc   = PERM(row, col);
        uint2 o;
        o.x = pk(v.x, v.y);
        o.y = pk(v.z, v.w);
        *(uint2*)(g_xb + (size_t)node * 1024 + row * 64 + pc) = o;
        *(uint2*)(g_x1 + (size_t)node * 1024 + row * 64 + pc) = z;
    }
}

// =========================================================
// K1: fk[p][o][c] = (1/O) * sum_kd FKB[p,o,kd] * FW[kd,c]  -> bf16 pairs
// =========================================================
__global__ void k_fk(const float* __restrict__ fkb, const float* __restrict__ fw) {
    __shared__ float s[KDD];
    const int po = blockIdx.x;
    const int t  = threadIdx.x;
    s[t]      = fkb[po * KDD + t];
    s[t + 32] = fkb[po * KDD + t + 32];
    __syncthreads();
    float a0 = 0.f, a1 = 0.f;
#pragma unroll 16
    for (int kd = 0; kd < KDD; kd++) {
        a0 += s[kd] * fw[kd * CC + 2 * t];
        a1 += s[kd] * fw[kd * CC + 2 * t + 1];
    }
    g_fkb[po * 32 + t] = __floats2bfloat162_rn(a0 * (1.0f / OO), a1 * (1.0f / OO));
}

// =========================================================
// K1b: pack kernel_w / w1 / w2 into mma B-fragment layout (bf16)
// Parallelized over 16 blocks x 8 warps = 128 warp-slots.
// =========================================================
__global__ void k_pack(const float* __restrict__ kw,
                       const float* __restrict__ w1,
                       const float* __restrict__ w2) {
    const int tid  = threadIdx.x;
    const int wrp  = tid >> 5, lane = tid & 31;
    const int g    = lane >> 2, tg = lane & 3;
    const int slot = blockIdx.x * 8 + wrp;      // 0..127
    for (int f = slot; f < 32; f += 128) {
        const int kt = f >> 3, nt = f & 7;
        const int k = kt * 16 + 2 * tg, n = nt * 8 + g;
        g_kwp[(f * 32 + lane) * 2 + 0] = pk(kw[k * 64 + n],       kw[(k + 1) * 64 + n]);
        g_kwp[(f * 32 + lane) * 2 + 1] = pk(kw[(k + 8) * 64 + n], kw[(k + 9) * 64 + n]);
    }
    for (int f = slot; f < 128; f += 128) {
        const int kt = f >> 5, nt = f & 31;
        const int k = kt * 16 + 2 * tg, n = nt * 8 + g;
        g_w1p[(f * 32 + lane) * 2 + 0] = pk(w1[k * 256 + n],       w1[(k + 1) * 256 + n]);
        g_w1p[(f * 32 + lane) * 2 + 1] = pk(w1[(k + 8) * 256 + n], w1[(k + 9) * 256 + n]);
    }
    for (int f = slot; f < 128; f += 128) {
        const int kt = f >> 3, nt = f & 7;
        const int k = kt * 16 + 2 * tg, n = nt * 8 + g;
        g_w2p[(f * 32 + lane) * 2 + 0] = pk(w2[k * 64 + n],       w2[(k + 1) * 64 + n]);
        g_w2p[(f * 32 + lane) * 2 + 1] = pk(w2[(k + 8) * 64 + n], w2[(k + 9) * 64 + n]);
    }
}

// =========================================================
// K2: edge conv. kb streamed with L2::evict_first; x from bf16 g_xb;
// msg built in-place in a double-buffered bf16 scatter buffer.
// 8 warps/block, 4 edges/warp, grid=3125.
// smem: Wp 8KB + KBS 16KB + XB 32KB = 56KB, 2 blocks/SM.
// =========================================================
__global__ void __launch_bounds__(256, 2) k_edge(
    const float* __restrict__ kb,
    const int*   __restrict__ ei)
{
    extern __shared__ float sme[];
    unsigned* Wp      = (unsigned*)sme;             // 2048 u32  (8KB)
    unsigned* KBS_all = Wp + 2048;                  // 4096 u32  (16KB) bf16 kb tiles
    unsigned* XB_all  = KBS_all + 4096;             // 8 warps x 2 x 512 u32 (32KB)

    const int tid  = threadIdx.x;
    const int wrp  = tid >> 5, lane = tid & 31;
    const int g    = lane >> 2, tg = lane & 3;

    for (int i = tid; i < 2048; i += 256) Wp[i] = g_kwp[i];
    __syncthreads();

    char*     KBS = (char*)(KBS_all + wrp * 512);   // 2KB bf16 tile, swizzled
    unsigned* XB  = XB_all + wrp * 1024;            // 2 x 2KB bf16 msg buffers

    // L2 eviction policy: kb is streamed once, keep xb/x1 resident
    unsigned long long pol;
    asm volatile("createpolicy.fractional.L2::evict_first.b64 %0, 1.0;" : "=l"(pol));

    const int lrow  = lane & 15;
    const int lhalf = lane >> 4;
    const unsigned kbs_base = (unsigned)__cvta_generic_to_shared(KBS);

#pragma unroll 1
    for (int it = 0; it < 4; ++it) {
        const int e   = blockIdx.x * 32 + wrp * 4 + it;
        const int src = ei[e];
        const int dst = ei[EE + e];

        // ---- coalesced loads: kb fp32 (evict_first) + xb bf16 ----
        const float4* kb4 = (const float4*)(kb + (size_t)e * TILE);
        const uint4*  xb4 = (const uint4*)(g_xb + (size_t)src * TILE);
        float4 kv[8];
        uint4  xv[4];
#pragma unroll
        for (int i = 0; i < 8; ++i)
            asm volatile("ld.global.nc.L2::cache_hint.v4.f32 {%0,%1,%2,%3}, [%4], %5;"
                         : "=f"(kv[i].x), "=f"(kv[i].y), "=f"(kv[i].z), "=f"(kv[i].w)
                         : "l"(kb4 + i * 32 + lane), "l"(pol));
#pragma unroll
        for (int i = 0; i < 4; ++i) xv[i] = xb4[i * 32 + lane];

        // ---- kb -> bf16 swizzled smem ----
#pragma unroll
        for (int i = 0; i < 8; ++i) {
            const int idx = i * 32 + lane;          // float4 index in tile
            const int row = idx >> 4;               // 0..15
            const int bc  = (idx & 15) * 8;         // byte col (0..120)
            const int bcs = bc ^ ((row & 7) << 4);  // SW128 swizzle
            uint2 v;
            v.x = pk(kv[i].x, kv[i].y);
            v.y = pk(kv[i].z, kv[i].w);
            *(uint2*)(KBS + row * 128 + bcs) = v;
        }

        const int buf = it & 1;
        unsigned* mb = XB + buf * 512;
        if (lane == 0 && it >= 2)
            asm volatile("cp.async.bulk.wait_group 1;" ::: "memory");
        __syncwarp();   // scatter of this buffer drained; KBS stores visible

        // ---- stage xb (already permuted) into msg buffer ----
#pragma unroll
        for (int i = 0; i < 4; ++i)
            ((uint4*)mb)[i * 32 + lane] = xv[i];
        __syncwarp();

        // ---- A fragments via ldmatrix ----
        unsigned A[4][4];
#pragma unroll
        for (int kt = 0; kt < 4; ++kt) {
            const int bc  = kt * 32 + lhalf * 16;
            const unsigned addr = kbs_base + lrow * 128 + (bc ^ ((lrow & 7) << 4));
            asm volatile(
                "ldmatrix.sync.aligned.m8n8.x4.shared.b16 {%0,%1,%2,%3}, [%4];"
                : "=r"(A[kt][0]), "=r"(A[kt][1]), "=r"(A[kt][2]), "=r"(A[kt][3])
                : "r"(addr));
        }

        float c[8][4];
#pragma unroll
        for (int nt = 0; nt < 8; ++nt)
            c[nt][0] = c[nt][1] = c[nt][2] = c[nt][3] = 0.f;
#pragma unroll
        for (int kt = 0; kt < 4; ++kt)
#pragma unroll
            for (int nt = 0; nt < 8; ++nt) {
                uint2 b = *(const uint2*)&Wp[((kt * 8 + nt) * 32 + lane) * 2];
                mma_bf16(c[nt], A[kt], b.x, b.y);
            }

        // ---- msg = x * k, in place (bf16 hmul2) ----
#pragma unroll
        for (int nt = 0; nt < 8; ++nt) {
            const int c0 = nt * 8 + 2 * tg;
            const int w  = PERM(g, c0) >> 1;        // bf162 word col (same for g, g+8)
            unsigned x0 = mb[g * 32 + w];
            unsigned x1 = mb[(g + 8) * 32 + w];
            unsigned k0 = pk(c[nt][0], c[nt][1]);
            unsigned k1 = pk(c[nt][2], c[nt][3]);
            __nv_bfloat162 m0 = __hmul2(*(__nv_bfloat162*)&x0, *(__nv_bfloat162*)&k0);
            __nv_bfloat162 m1 = __hmul2(*(__nv_bfloat162*)&x1, *(__nv_bfloat162*)&k1);
            mb[g * 32 + w]       = *(unsigned*)&m0;
            mb[(g + 8) * 32 + w] = *(unsigned*)&m1;
        }
        __syncwarp();

        if (lane == 0) {
            asm volatile("fence.proxy.async.shared::cta;" ::: "memory");
            unsigned saddr = (unsigned)__cvta_generic_to_shared(mb);
            char* gptr = (char*)g_x1 + (size_t)dst * 2048;
            asm volatile(
                "cp.reduce.async.bulk.global.shared::cta.bulk_group.add.noftz.bf16 [%0], [%1], %2;"
                :: "l"(gptr), "r"(saddr), "r"(2048) : "memory");
            asm volatile("cp.async.bulk.commit_group;" ::: "memory");
        }
    }
    if (lane == 0)
        asm volatile("cp.async.bulk.wait_group 0;" ::: "memory");
    __syncwarp();
}

// =========================================================
// K3: persistent fused fiber conv + LN + bf16-MMA MLP + residual
// grid=148, 512 threads. x1 tiles prefetched via cp.async.bulk (double buffer),
// fk in registers, per-node-pair named barrier between MLP1/MLP2,
// epilogue staged through x2 smem for fully coalesced residual+store.
// =========================================================
#define X2S 68                                 // x2 row stride (float4-aligned)
#define FUSE_SMEM_FLOATS (8192*2 + 128*X2S + 128 + 128 + 256 + 64*5 + 4 + 16896 + 8192)
#define FUSE_SMEM_BYTES  (FUSE_SMEM_FLOATS * 4)

__global__ void __launch_bounds__(512, 1) k_fuse(
    const float* __restrict__ x,
    const float* __restrict__ cb,
    const float* __restrict__ lns,
    const float* __restrict__ lnb,
    const float* __restrict__ b1,
    const float* __restrict__ b2,
    const float* __restrict__ ls,
    float*       __restrict__ out)
{
    extern __shared__ float sm[];
    unsigned* w1p  = (unsigned*)sm;                    // 8192 u32 (32KB)
    unsigned* w2p  = w1p + 8192;                       // 8192 u32 (32KB)
    float* x2    = (float*)(w2p + 8192);               // 128 x 68 f32 (34.8KB)
    float* mu_s  = x2 + 128 * X2S;                     // 128
    float* rs_s  = mu_s + 128;                         // 128
    float* b1_s  = rs_s + 128;                         // 256
    float* b2_s  = b1_s + 256;                         // 64
    float* ls_s  = b2_s + 64;                          // 64
    float* lns_s = ls_s + 64;                          // 64
    float* lnb_s = lns_s + 64;                         // 64
    float* cb_s  = lnb_s + 64;                         // 64
    unsigned long long* mbar = (unsigned long long*)(cb_s + 64);  // 2 mbarriers (16B)
    unsigned* h1 = (unsigned*)(mbar + 2);              // 128 x 132 u32 (66KB)
    __nv_bfloat16* stage = (__nv_bfloat16*)(h1 + 16896); // 2 x 8192 bf16 (32KB)

    const int tid  = threadIdx.x;
    const int wrp  = tid >> 5, lane = tid & 31;
    const int g    = lane >> 2, tg = lane & 3;
    const int nloc = wrp >> 1;        // 0..7: node within group
    const int sub  = wrp & 1;         // warp's half of the MLP

    const unsigned mb0 = (unsigned)__cvta_generic_to_shared(&mbar[0]);
    const unsigned mb1 = (unsigned)__cvta_generic_to_shared(&mbar[1]);

    for (int i = tid; i < 8192; i += 512) {
        w1p[i] = g_w1p[i];
        w2p[i] = g_w2p[i];
    }
    if (tid < 64) {
        b2_s[tid]  = b2[tid];
        ls_s[tid]  = ls[tid] * 1e-6f;   // fold LS_VAL
        lns_s[tid] = lns[tid];
        lnb_s[tid] = lnb[tid];
        cb_s[tid]  = cb[tid];
    }
    if (tid < 256) b1_s[tid] = b1[tid];
    if (tid == 0) {
        asm volatile("mbarrier.init.shared.b64 [%0], 1;" :: "r"(mb0) : "memory");
        asm volatile("mbarrier.init.shared.b64 [%0], 1;" :: "r"(mb1) : "memory");
    }

    // ---- hoist fiber kernel into registers: thread = (c4, p, half) ----
    const int c4 = tid & 15, fp_ = (tid >> 4) & 15, half = tid >> 8;
    __nv_bfloat162 fkr0[16], fkr1[16];
#pragma unroll
    for (int o = 0; o < 16; ++o) {
        uint2 v = *(const uint2*)&((const unsigned*)g_fkb)[fp_ * 512 + o * 32 + 2 * c4];
        fkr0[o] = *reinterpret_cast<__nv_bfloat162*>(&v.x);
        fkr1[o] = *reinterpret_cast<__nv_bfloat162*>(&v.y);
    }
    __syncthreads();
    const float4 cbv = *(const float4*)&cb_s[4 * c4];

    // ---- prologue: prefetch first group's x1 tile into stage buf 0 ----
    if (tid == 0) {
        asm volatile("mbarrier.arrive.expect_tx.shared.b64 _, [%0], 16384;" :: "r"(mb0) : "memory");
        unsigned sdst = (unsigned)__cvta_generic_to_shared(stage);
        const char* gsrc = (const char*)g_x1 + (size_t)blockIdx.x * 16384;
        asm volatile(
            "cp.async.bulk.shared::cta.global.mbarrier::complete_tx::bytes [%0], [%1], 16384, [%2];"
            :: "r"(sdst), "l"(gsrc), "r"(mb0) : "memory");
    }

    int ph0 = 0, ph1 = 0;
    int it = 0;
#pragma unroll 1
    for (int grp = blockIdx.x; grp < NGRP; grp += 148, ++it) {
        const int nodebase = grp * 8;
        const int buf = it & 1;
        const __nv_bfloat16* stg = stage + buf * 8192;

        // ---- wait for this group's x1 tile ----
        if (buf == 0) { mbar_wait(mb0, ph0); ph0 ^= 1; }
        else          { mbar_wait(mb1, ph1); ph1 ^= 1; }

        // ---- fiber conv (bf162 hfma2, fk in regs): 4 nodes per thread ----
#pragma unroll
        for (int n = 0; n < 4; ++n) {
            const int node = half * 4 + n;
            const __nv_bfloat16* sp = stg + node * 1024;
            __nv_bfloat162 acc0 = __floats2bfloat162_rn(0.f, 0.f);
            __nv_bfloat162 acc1 = acc0;
#pragma unroll
            for (int o = 0; o < 16; ++o) {
                uint2 xv = *(const uint2*)(sp + o * 64 + PERM(o, 4 * c4));
                acc0 = __hfma2(*reinterpret_cast<__nv_bfloat162*>(&xv.x), fkr0[o], acc0);
                acc1 = __hfma2(*reinterpret_cast<__nv_bfloat162*>(&xv.y), fkr1[o], acc1);
            }
            float2 a0 = __bfloat1622float2(acc0);
            float2 a1 = __bfloat1622float2(acc1);
            *(float4*)&x2[(node * 16 + fp_) * X2S + 4 * c4] =
                make_float4(a0.x + cbv.x, a0.y + cbv.y, a1.x + cbv.z, a1.y + cbv.w);
        }
        __syncthreads();   // x2 ready; everyone done reading stage[buf]

        // ---- prefetch next group's x1 into the other buffer ----
        if (tid == 0 && grp + 148 < NGRP) {
            const unsigned mbn = (buf == 0) ? mb1 : mb0;
            asm volatile("mbarrier.arrive.expect_tx.shared.b64 _, [%0], 16384;" :: "r"(mbn) : "memory");
            unsigned sdst = (unsigned)__cvta_generic_to_shared(stage + (buf ^ 1) * 8192);
            const char* gsrc = (const char*)g_x1 + (size_t)(grp + 148) * 16384;
            asm volatile(
                "cp.async.bulk.shared::cta.global.mbarrier::complete_tx::bytes [%0], [%1], 16384, [%2];"
                :: "r"(sdst), "l"(gsrc), "r"(mbn) : "memory");
        }

        // ---- LayerNorm stats: 4 threads per row (float4, aligned via X2S=68) ----
        {
            const int row = tid >> 2, q = tid & 3;
            const float* xr = x2 + row * X2S + q * 16;
            float s = 0.f, ss = 0.f;
#pragma unroll
            for (int j = 0; j < 4; ++j) {
                float4 v = *(const float4*)(xr + j * 4);
                s  += v.x + v.y + v.z + v.w;
                ss += v.x * v.x + v.y * v.y + v.z * v.z + v.w * v.w;
            }
            s  += __shfl_xor_sync(0xffffffffu, s, 1);
            ss += __shfl_xor_sync(0xffffffffu, ss, 1);
            s  += __shfl_xor_sync(0xffffffffu, s, 2);
            ss += __shfl_xor_sync(0xffffffffu, ss, 2);
            if (q == 0) {
                const float mu  = s * (1.f / 64.f);
                const float var = ss * (1.f / 64.f) - mu * mu;
                mu_s[row] = mu;
                rs_s[row] = rsqrtf(var + 1e-6f);
            }
        }
        __syncthreads();

        // ---- build normalized A fragments ----
        const int r0  = nloc * 16 + g;
        const float mu0 = mu_s[r0],     rs0 = rs_s[r0];
        const float mu1 = mu_s[r0 + 8], rs1 = rs_s[r0 + 8];
        unsigned A[4][4];
#pragma unroll
        for (int kt = 0; kt < 4; ++kt) {
            const int k0 = kt * 16 + 2 * tg;
            float2 sc0 = *(float2*)(lns_s + k0),     bi0 = *(float2*)(lnb_s + k0);
            float2 sc1 = *(float2*)(lns_s + k0 + 8), bi1 = *(float2*)(lnb_s + k0 + 8);
            float2 v;
            v = *(float2*)(x2 + r0 * X2S + k0);
            A[kt][0] = pk((v.x - mu0) * rs0 * sc0.x + bi0.x, (v.y - mu0) * rs0 * sc0.y + bi0.y);
            v = *(float2*)(x2 + (r0 + 8) * X2S + k0);
            A[kt][1] = pk((v.x - mu1) * rs1 * sc0.x + bi0.x, (v.y - mu1) * rs1 * sc0.y + bi0.y);
            v = *(float2*)(x2 + r0 * X2S + k0 + 8);
            A[kt][2] = pk((v.x - mu0) * rs0 * sc1.x + bi1.x, (v.y - mu0) * rs0 * sc1.y + bi1.y);
            v = *(float2*)(x2 + (r0 + 8) * X2S + k0 + 8);
            A[kt][3] = pk((v.x - mu1) * rs1 * sc1.x + bi1.x, (v.y - mu1) * rs1 * sc1.y + bi1.y);
        }

        // ---- MLP1: this warp's half (16 of 32 n-tiles) ----
        {
            float c1r[16][4];
#pragma unroll
            for (int nt = 0; nt < 16; ++nt) {
                const int col = (sub * 16 + nt) * 8 + 2 * tg;
                c1r[nt][0] = b1_s[col]; c1r[nt][1] = b1_s[col + 1];
                c1r[nt][2] = b1_s[col]; c1r[nt][3] = b1_s[col + 1];
            }
#pragma unroll
            for (int kt = 0; kt < 4; ++kt)
#pragma unroll
                for (int nt = 0; nt < 16; ++nt) {
                    const int ntg = sub * 16 + nt;
                    uint2 b = *(const uint2*)&w1p[((kt * 32 + ntg) * 32 + lane) * 2];
                    mma_bf16(c1r[nt], A[kt], b.x, b.y);
                }
#pragma unroll
            for (int nt = 0; nt < 16; ++nt) {
                const int ntg = sub * 16 + nt;
                const float p0 = fmaxf(c1r[nt][0], 0.f), p1 = fmaxf(c1r[nt][1], 0.f);
                const float p2 = fmaxf(c1r[nt][2], 0.f), p3 = fmaxf(c1r[nt][3], 0.f);
                h1[r0 * 132 + ntg * 4 + tg]       = pk(p0, p1);
                h1[(r0 + 8) * 132 + ntg * 4 + tg] = pk(p2, p3);
            }
        }
        // h1 is node-pair local: named barrier over the pair's 64 threads
        asm volatile("bar.sync %0, 64;" :: "r"(1 + nloc) : "memory");

        // ---- MLP2: this warp's quarter (4 of 8 n-tiles) ----
        float d[4][4];
#pragma unroll
        for (int nt = 0; nt < 4; ++nt) {
            const int col = (sub * 4 + nt) * 8 + 2 * tg;
            d[nt][0] = b2_s[col]; d[nt][1] = b2_s[col + 1];
            d[nt][2] = b2_s[col]; d[nt][3] = b2_s[col + 1];
        }
#pragma unroll
        for (int kt = 0; kt < 16; ++kt) {
            unsigned a[4];
            a[0] = h1[r0 * 132 + kt * 8 + tg];
            a[1] = h1[(r0 + 8) * 132 + kt * 8 + tg];
            a[2] = h1[r0 * 132 + kt * 8 + 4 + tg];
            a[3] = h1[(r0 + 8) * 132 + kt * 8 + 4 + tg];
#pragma unroll
            for (int nt = 0; nt < 4; ++nt) {
                uint2 b = *(const uint2*)&w2p[((kt * 8 + sub * 4 + nt) * 32 + lane) * 2];
                mma_bf16(d[nt], a, b.x, b.y);
            }
        }

        // ---- epilogue part 1: scaled d -> x2 smem (own rows only) ----
#pragma unroll
        for (int nt = 0; nt < 4; ++nt) {
            const int col = (sub * 4 + nt) * 8 + 2 * tg;
            const float l0 = ls_s[col], l1 = ls_s[col + 1];
            *(float2*)&x2[r0 * X2S + col] =
                make_float2(l0 * d[nt][0], l1 * d[nt][1]);
            *(float2*)&x2[(r0 + 8) * X2S + col] =
                make_float2(l0 * d[nt][2], l1 * d[nt][3]);
        }
        __syncthreads();   // all pairs done writing scaled outputs

        // ---- epilogue part 2: coalesced out = x2 + x (float4) ----
        {
            const float4* xr4 = (const float4*)(x + (size_t)nodebase * TILE);
            float4* o4 = (float4*)(out + (size_t)nodebase * TILE);
#pragma unroll
            for (int i = 0; i < 4; ++i) {
                const int j   = tid + i * 512;       // float4 index in 8-node tile
                const int row = j >> 4;              // 0..127 == x2 row
                const int col = (j & 15) * 4;
                float4 xv = xr4[j];
                const float* xp = &x2[row * X2S + col];
                o4[j] = make_float4(xp[0] + xv.x, xp[1] + xv.y,
                                    xp[2] + xv.z, xp[3] + xv.w);
            }
        }
        __syncthreads();   // protect x2/h1 for next group
    }
}

// =========================================================
extern "C" void kernel_launch(void* const* d_in, const int* in_sizes, int n_in,
                              void* d_out, int out_size)
{
    (void)in_sizes; (void)n_in; (void)out_size;
    const float* x   = (const float*)d_in[0];
    const float* kb  = (const float*)d_in[1];
    const float* fkb = (const float*)d_in[2];
    const int*   ei  = (const int*)  d_in[3];
    const float* kw  = (const float*)d_in[4];
    const float* fkw = (const float*)d_in[5];
    const float* cb  = (const float*)d_in[6];
    const float* lns = (const float*)d_in[7];
    const float* lnb = (const float*)d_in[8];
    const float* w1  = (const float*)d_in[9];
    const float* b1  = (const float*)d_in[10];
    const float* w2  = (const float*)d_in[11];
    const float* b2  = (const float*)d_in[12];
    const float* ls  = (const float*)d_in[13];
    float* out = (float*)d_out;

    const int edge_smem = 57344;   // 56KB: Wp 8K + KBS 16K + XB 32K
    cudaFuncSetAttribute(k_edge, cudaFuncAttributeMaxDynamicSharedMemorySize, edge_smem);
    cudaFuncSetAttribute(k_fuse, cudaFuncAttributeMaxDynamicSharedMemorySize, FUSE_SMEM_BYTES);

    k_prep0<<<2560, 256>>>(x);
    k_fk<<<OO * OO, 32>>>(fkb, fkw);
    k_pack<<<16, 256>>>(kw, w1, w2);
    k_edge<<<EE / 32, 256, edge_smem>>>(kb, ei);
    k_fuse<<<148, 512, FUSE_SMEM_BYTES>>>(x, cb, lns, lnb, b1, b2, ls, out);
}

// round 15
// speedup vs baseline: 8.0150x; 1.0698x over previous
#include <cuda_runtime.h>
#include <cuda_bf16.h>

#define NN   10000
#define OO   16
#define CC   64
#define EE   100000
#define KDD  64
#define NOC  (NN*OO*CC)          // 10,240,000
#define TILE (OO*CC)             // 1024 elements per node/edge tile
#define NGRP (NN/8)              // 1250 groups of 8 nodes

// column permutation applied to g_x1 / g_xb tiles (element index within a 64-elem row)
#define PERM(row, col) ((col) ^ (((row) & 3) << 3))

// -------- device scratch (no allocations allowed) --------
__device__ __align__(16) __nv_bfloat16  g_x1[NOC];      // 20.5 MB spatial-conv accumulator (bf16, PERMuted)
__device__ __align__(16) __nv_bfloat16  g_xb[NOC];      // 20.5 MB bf16 permuted copy of x
__device__ __align__(16) __nv_bfloat162 g_fkb[8192];    // fiber kernel bf16 (pre /O)
__device__ __align__(16) unsigned       g_kwp[2048];    // kernel_w  B-frags (4kt x 8nt)
__device__ __align__(16) unsigned       g_w1p[8192];    // w1 B-frags (4kt x 32nt)
__device__ __align__(16) unsigned       g_w2p[8192];    // w2 B-frags (16kt x 8nt)

// -------- helpers --------
__device__ __forceinline__ unsigned pk(float lo, float hi) {
    __nv_bfloat162 t = __floats2bfloat162_rn(lo, hi);   // .x = lo (low 16 bits)
    return *reinterpret_cast<unsigned*>(&t);
}

__device__ __forceinline__ void mma_bf16(float* c, const unsigned* a, unsigned b0, unsigned b1) {
    asm volatile(
        "mma.sync.aligned.m16n8k16.row.col.f32.bf16.bf16.f32 "
        "{%0,%1,%2,%3}, {%4,%5,%6,%7}, {%8,%9}, {%0,%1,%2,%3};"
        : "+f"(c[0]), "+f"(c[1]), "+f"(c[2]), "+f"(c[3])
        : "r"(a[0]), "r"(a[1]), "r"(a[2]), "r"(a[3]), "r"(b0), "r"(b1));
}

__device__ __forceinline__ void mbar_wait(unsigned mbar, int phase) {
    asm volatile(
        "{\n\t.reg .pred P1;\n\t"
        "WAIT_LOOP_%=:\n\t"
        "mbarrier.try_wait.parity.acquire.cta.shared::cta.b64 P1, [%0], %1, 0x989680;\n\t"
        "@P1 bra.uni WAIT_DONE_%=;\n\t"
        "bra.uni WAIT_LOOP_%=;\n\t"
        "WAIT_DONE_%=:\n\t}"
        :: "r"(mbar), "r"(phase) : "memory");
}

// =========================================================
// K0: fused prep — zero g_x1 AND build g_xb (bf16 permuted x) in one pass
// =========================================================
__global__ void k_prep0(const float* __restrict__ x) {
    const int n4 = NOC / 4;          // 2,560,000 float4s
    int i = blockIdx.x * blockDim.x + threadIdx.x;
    const int stride = gridDim.x * blockDim.x;
    const uint2 z = make_uint2(0u, 0u);
    for (; i < n4; i += stride) {
        float4 v = ((const float4*)x)[i];
        const int node = i >> 8;
        const int f    = (i & 255) * 4;      // element index within tile
        const int row  = f >> 6, col = f & 63;
        const int pc   = PERM(row, col);
        uint2 o;
        o.x = pk(v.x, v.y);
        o.y = pk(v.z, v.w);
        *(uint2*)(g_xb + (size_t)node * 1024 + row * 64 + pc) = o;
        *(uint2*)(g_x1 + (size_t)node * 1024 + row * 64 + pc) = z;
    }
}

// =========================================================
// K1: fk[p][o][c] = (1/O) * sum_kd FKB[p,o,kd] * FW[kd,c]  -> bf16 pairs
// =========================================================
__global__ void k_fk(const float* __restrict__ fkb, const float* __restrict__ fw) {
    __shared__ float s[KDD];
    const int po = blockIdx.x;
    const int t  = threadIdx.x;
    s[t]      = fkb[po * KDD + t];
    s[t + 32] = fkb[po * KDD + t + 32];
    __syncthreads();
    float a0 = 0.f, a1 = 0.f;
#pragma unroll 16
    for (int kd = 0; kd < KDD; kd++) {
        a0 += s[kd] * fw[kd * CC + 2 * t];
        a1 += s[kd] * fw[kd * CC + 2 * t + 1];
    }
    g_fkb[po * 32 + t] = __floats2bfloat162_rn(a0 * (1.0f / OO), a1 * (1.0f / OO));
}

// =========================================================
// K1b: pack kernel_w / w1 / w2 into mma B-fragment layout (bf16)
// Parallelized over 16 blocks x 8 warps = 128 warp-slots.
// =========================================================
__global__ void k_pack(const float* __restrict__ kw,
                       const float* __restrict__ w1,
                       const float* __restrict__ w2) {
    const int tid  = threadIdx.x;
    const int wrp  = tid >> 5, lane = tid & 31;
    const int g    = lane >> 2, tg = lane & 3;
    const int slot = blockIdx.x * 8 + wrp;      // 0..127
    for (int f = slot; f < 32; f += 128) {
        const int kt = f >> 3, nt = f & 7;
        const int k = kt * 16 + 2 * tg, n = nt * 8 + g;
        g_kwp[(f * 32 + lane) * 2 + 0] = pk(kw[k * 64 + n],       kw[(k + 1) * 64 + n]);
        g_kwp[(f * 32 + lane) * 2 + 1] = pk(kw[(k + 8) * 64 + n], kw[(k + 9) * 64 + n]);
    }
    for (int f = slot; f < 128; f += 128) {
        const int kt = f >> 5, nt = f & 31;
        const int k = kt * 16 + 2 * tg, n = nt * 8 + g;
        g_w1p[(f * 32 + lane) * 2 + 0] = pk(w1[k * 256 + n],       w1[(k + 1) * 256 + n]);
        g_w1p[(f * 32 + lane) * 2 + 1] = pk(w1[(k + 8) * 256 + n], w1[(k + 9) * 256 + n]);
    }
    for (int f = slot; f < 128; f += 128) {
        const int kt = f >> 3, nt = f & 7;
        const int k = kt * 16 + 2 * tg, n = nt * 8 + g;
        g_w2p[(f * 32 + lane) * 2 + 0] = pk(w2[k * 64 + n],       w2[(k + 1) * 64 + n]);
        g_w2p[(f * 32 + lane) * 2 + 1] = pk(w2[(k + 8) * 64 + n], w2[(k + 9) * 64 + n]);
    }
}

// =========================================================
// K2: edge conv. kb streamed with L2::evict_first; x from bf16 g_xb;
// msg built in-place in a double-buffered bf16 scatter buffer.
// Register-dieted (chunked loads, 2-pass accumulators) for 3 blocks/SM.
// 8 warps/block, 4 edges/warp, grid=3125.
// smem: Wp 8KB + KBS 16KB + XB 32KB = 56KB, 3 blocks/SM.
// =========================================================
__global__ void __launch_bounds__(256, 3) k_edge(
    const float* __restrict__ kb,
    const int*   __restrict__ ei)
{
    extern __shared__ float sme[];
    unsigned* Wp      = (unsigned*)sme;             // 2048 u32  (8KB)
    unsigned* KBS_all = Wp + 2048;                  // 4096 u32  (16KB) bf16 kb tiles
    unsigned* XB_all  = KBS_all + 4096;             // 8 warps x 2 x 512 u32 (32KB)

    const int tid  = threadIdx.x;
    const int wrp  = tid >> 5, lane = tid & 31;
    const int g    = lane >> 2, tg = lane & 3;

    for (int i = tid; i < 2048; i += 256) Wp[i] = g_kwp[i];
    __syncthreads();

    char*     KBS = (char*)(KBS_all + wrp * 512);   // 2KB bf16 tile, swizzled
    unsigned* XB  = XB_all + wrp * 1024;            // 2 x 2KB bf16 msg buffers

    // L2 eviction policy: kb is streamed once, keep xb/x1 resident
    unsigned long long pol;
    asm volatile("createpolicy.fractional.L2::evict_first.b64 %0, 1.0;" : "=l"(pol));

    const int lrow  = lane & 15;
    const int lhalf = lane >> 4;
    const unsigned kbs_base = (unsigned)__cvta_generic_to_shared(KBS);

#pragma unroll 1
    for (int it = 0; it < 4; ++it) {
        const int e   = blockIdx.x * 32 + wrp * 4 + it;
        const int src = ei[e];
        const int dst = ei[EE + e];

        const int buf = it & 1;
        unsigned* mb = XB + buf * 512;
        // drain scatter that used this buffer (issued 2 iterations ago)
        if (lane == 0 && it >= 2)
            asm volatile("cp.async.bulk.wait_group 1;" ::: "memory");
        __syncwarp();

        // ---- kb -> bf16 swizzled smem, 2 chunks of 4 float4 ----
        const float4* kb4 = (const float4*)(kb + (size_t)e * TILE);
#pragma unroll
        for (int ch = 0; ch < 2; ++ch) {
            float4 kv[4];
#pragma unroll
            for (int i = 0; i < 4; ++i)
                asm volatile("ld.global.nc.L2::cache_hint.v4.f32 {%0,%1,%2,%3}, [%4], %5;"
                             : "=f"(kv[i].x), "=f"(kv[i].y), "=f"(kv[i].z), "=f"(kv[i].w)
                             : "l"(kb4 + (ch * 4 + i) * 32 + lane), "l"(pol));
#pragma unroll
            for (int i = 0; i < 4; ++i) {
                const int idx = (ch * 4 + i) * 32 + lane;   // float4 index in tile
                const int row = idx >> 4;                   // 0..15
                const int bc  = (idx & 15) * 8;             // byte col (0..120)
                const int bcs = bc ^ ((row & 7) << 4);      // SW128 swizzle
                uint2 v;
                v.x = pk(kv[i].x, kv[i].y);
                v.y = pk(kv[i].z, kv[i].w);
                *(uint2*)(KBS + row * 128 + bcs) = v;
            }
        }

        // ---- xb (already permuted bf16) -> msg buffer, 2 chunks of 2 uint4 ----
        const uint4* xb4 = (const uint4*)(g_xb + (size_t)src * TILE);
#pragma unroll
        for (int ch = 0; ch < 2; ++ch) {
            uint4 xv[2];
#pragma unroll
            for (int i = 0; i < 2; ++i) xv[i] = xb4[(ch * 2 + i) * 32 + lane];
#pragma unroll
            for (int i = 0; i < 2; ++i) ((uint4*)mb)[(ch * 2 + i) * 32 + lane] = xv[i];
        }
        __syncwarp();   // KBS + mb staging visible warp-wide

        // ---- A fragments via ldmatrix ----
        unsigned A[4][4];
#pragma unroll
        for (int kt = 0; kt < 4; ++kt) {
            const int bc  = kt * 32 + lhalf * 16;
            const unsigned addr = kbs_base + lrow * 128 + (bc ^ ((lrow & 7) << 4));
            asm volatile(
                "ldmatrix.sync.aligned.m8n8.x4.shared.b16 {%0,%1,%2,%3}, [%4];"
                : "=r"(A[kt][0]), "=r"(A[kt][1]), "=r"(A[kt][2]), "=r"(A[kt][3])
                : "r"(addr));
        }

        // ---- 2 passes of 4 n-tiles: mma then in-place msg hmul ----
#pragma unroll 1
        for (int pass = 0; pass < 2; ++pass) {
            float c[4][4];
#pragma unroll
            for (int ntl = 0; ntl < 4; ++ntl)
                c[ntl][0] = c[ntl][1] = c[ntl][2] = c[ntl][3] = 0.f;
#pragma unroll
            for (int kt = 0; kt < 4; ++kt)
#pragma unroll
                for (int ntl = 0; ntl < 4; ++ntl) {
                    const int nt = pass * 4 + ntl;
                    uint2 b = *(const uint2*)&Wp[((kt * 8 + nt) * 32 + lane) * 2];
                    mma_bf16(c[ntl], A[kt], b.x, b.y);
                }
#pragma unroll
            for (int ntl = 0; ntl < 4; ++ntl) {
                const int nt = pass * 4 + ntl;
                const int c0 = nt * 8 + 2 * tg;
                const int w  = PERM(g, c0) >> 1;    // bf162 word col (same for g, g+8)
                unsigned x0 = mb[g * 32 + w];
                unsigned x1 = mb[(g + 8) * 32 + w];
                unsigned k0 = pk(c[ntl][0], c[ntl][1]);
                unsigned k1 = pk(c[ntl][2], c[ntl][3]);
                __nv_bfloat162 m0 = __hmul2(*(__nv_bfloat162*)&x0, *(__nv_bfloat162*)&k0);
                __nv_bfloat162 m1 = __hmul2(*(__nv_bfloat162*)&x1, *(__nv_bfloat162*)&k1);
                mb[g * 32 + w]       = *(unsigned*)&m0;
                mb[(g + 8) * 32 + w] = *(unsigned*)&m1;
            }
        }
        __syncwarp();

        if (lane == 0) {
            asm volatile("fence.proxy.async.shared::cta;" ::: "memory");
            unsigned saddr = (unsigned)__cvta_generic_to_shared(mb);
            char* gptr = (char*)g_x1 + (size_t)dst * 2048;
            asm volatile(
                "cp.reduce.async.bulk.global.shared::cta.bulk_group.add.noftz.bf16 [%0], [%1], %2;"
                :: "l"(gptr), "r"(saddr), "r"(2048) : "memory");
            asm volatile("cp.async.bulk.commit_group;" ::: "memory");
        }
    }
    if (lane == 0)
        asm volatile("cp.async.bulk.wait_group 0;" ::: "memory");
    __syncwarp();
}

// =========================================================
// K3: persistent fused fiber conv + LN + bf16-MMA MLP + residual
// grid=148, 512 threads. x1 tiles prefetched via cp.async.bulk (double buffer),
// fk in registers, per-node-pair named barrier between MLP1/MLP2,
// epilogue staged through x2 smem for fully coalesced residual+store.
// =========================================================
#define X2S 68                                 // x2 row stride (float4-aligned)
#define FUSE_SMEM_FLOATS (8192*2 + 128*X2S + 128 + 128 + 256 + 64*5 + 4 + 16896 + 8192)
#define FUSE_SMEM_BYTES  (FUSE_SMEM_FLOATS * 4)

__global__ void __launch_bounds__(512, 1) k_fuse(
    const float* __restrict__ x,
    const float* __restrict__ cb,
    const float* __restrict__ lns,
    const float* __restrict__ lnb,
    const float* __restrict__ b1,
    const float* __restrict__ b2,
    const float* __restrict__ ls,
    float*       __restrict__ out)
{
    extern __shared__ float sm[];
    unsigned* w1p  = (unsigned*)sm;                    // 8192 u32 (32KB)
    unsigned* w2p  = w1p + 8192;                       // 8192 u32 (32KB)
    float* x2    = (float*)(w2p + 8192);               // 128 x 68 f32 (34.8KB)
    float* mu_s  = x2 + 128 * X2S;                     // 128
    float* rs_s  = mu_s + 128;                         // 128
    float* b1_s  = rs_s + 128;                         // 256
    float* b2_s  = b1_s + 256;                         // 64
    float* ls_s  = b2_s + 64;                          // 64
    float* lns_s = ls_s + 64;                          // 64
    float* lnb_s = lns_s + 64;                         // 64
    float* cb_s  = lnb_s + 64;                         // 64
    unsigned long long* mbar = (unsigned long long*)(cb_s + 64);  // 2 mbarriers (16B)
    unsigned* h1 = (unsigned*)(mbar + 2);              // 128 x 132 u32 (66KB)
    __nv_bfloat16* stage = (__nv_bfloat16*)(h1 + 16896); // 2 x 8192 bf16 (32KB)

    const int tid  = threadIdx.x;
    const int wrp  = tid >> 5, lane = tid & 31;
    const int g    = lane >> 2, tg = lane & 3;
    const int nloc = wrp >> 1;        // 0..7: node within group
    const int sub  = wrp & 1;         // warp's half of the MLP

    const unsigned mb0 = (unsigned)__cvta_generic_to_shared(&mbar[0]);
    const unsigned mb1 = (unsigned)__cvta_generic_to_shared(&mbar[1]);

    for (int i = tid; i < 8192; i += 512) {
        w1p[i] = g_w1p[i];
        w2p[i] = g_w2p[i];
    }
    if (tid < 64) {
        b2_s[tid]  = b2[tid];
        ls_s[tid]  = ls[tid] * 1e-6f;   // fold LS_VAL
        lns_s[tid] = lns[tid];
        lnb_s[tid] = lnb[tid];
        cb_s[tid]  = cb[tid];
    }
    if (tid < 256) b1_s[tid] = b1[tid];
    if (tid == 0) {
        asm volatile("mbarrier.init.shared.b64 [%0], 1;" :: "r"(mb0) : "memory");
        asm volatile("mbarrier.init.shared.b64 [%0], 1;" :: "r"(mb1) : "memory");
    }

    // ---- hoist fiber kernel into registers: thread = (c4, p, half) ----
    const int c4 = tid & 15, fp_ = (tid >> 4) & 15, half = tid >> 8;
    __nv_bfloat162 fkr0[16], fkr1[16];
#pragma unroll
    for (int o = 0; o < 16; ++o) {
        uint2 v = *(const uint2*)&((const unsigned*)g_fkb)[fp_ * 512 + o * 32 + 2 * c4];
        fkr0[o] = *reinterpret_cast<__nv_bfloat162*>(&v.x);
        fkr1[o] = *reinterpret_cast<__nv_bfloat162*>(&v.y);
    }
    __syncthreads();
    const float4 cbv = *(const float4*)&cb_s[4 * c4];

    // ---- prologue: prefetch first group's x1 tile into stage buf 0 ----
    if (tid == 0) {
        asm volatile("mbarrier.arrive.expect_tx.shared.b64 _, [%0], 16384;" :: "r"(mb0) : "memory");
        unsigned sdst = (unsigned)__cvta_generic_to_shared(stage);
        const char* gsrc = (const char*)g_x1 + (size_t)blockIdx.x * 16384;
        asm volatile(
            "cp.async.bulk.shared::cta.global.mbarrier::complete_tx::bytes [%0], [%1], 16384, [%2];"
            :: "r"(sdst), "l"(gsrc), "r"(mb0) : "memory");
    }

    int ph0 = 0, ph1 = 0;
    int it = 0;
#pragma unroll 1
    for (int grp = blockIdx.x; grp < NGRP; grp += 148, ++it) {
        const int nodebase = grp * 8;
        const int buf = it & 1;
        const __nv_bfloat16* stg = stage + buf * 8192;

        // ---- wait for this group's x1 tile ----
        if (buf == 0) { mbar_wait(mb0, ph0); ph0 ^= 1; }
        else          { mbar_wait(mb1, ph1); ph1 ^= 1; }

        // ---- fiber conv (bf162 hfma2, fk in regs): 4 nodes per thread ----
#pragma unroll
        for (int n = 0; n < 4; ++n) {
            const int node = half * 4 + n;
            const __nv_bfloat16* sp = stg + node * 1024;
            __nv_bfloat162 acc0 = __floats2bfloat162_rn(0.f, 0.f);
            __nv_bfloat162 acc1 = acc0;
#pragma unroll
            for (int o = 0; o < 16; ++o) {
                uint2 xv = *(const uint2*)(sp + o * 64 + PERM(o, 4 * c4));
                acc0 = __hfma2(*reinterpret_cast<__nv_bfloat162*>(&xv.x), fkr0[o], acc0);
                acc1 = __hfma2(*reinterpret_cast<__nv_bfloat162*>(&xv.y), fkr1[o], acc1);
            }
            float2 a0 = __bfloat1622float2(acc0);
            float2 a1 = __bfloat1622float2(acc1);
            *(float4*)&x2[(node * 16 + fp_) * X2S + 4 * c4] =
                make_float4(a0.x + cbv.x, a0.y + cbv.y, a1.x + cbv.z, a1.y + cbv.w);
        }
        __syncthreads();   // x2 ready; everyone done reading stage[buf]

        // ---- prefetch next group's x1 into the other buffer ----
        if (tid == 0 && grp + 148 < NGRP) {
            const unsigned mbn = (buf == 0) ? mb1 : mb0;
            asm volatile("mbarrier.arrive.expect_tx.shared.b64 _, [%0], 16384;" :: "r"(mbn) : "memory");
            unsigned sdst = (unsigned)__cvta_generic_to_shared(stage + (buf ^ 1) * 8192);
            const char* gsrc = (const char*)g_x1 + (size_t)(grp + 148) * 16384;
            asm volatile(
                "cp.async.bulk.shared::cta.global.mbarrier::complete_tx::bytes [%0], [%1], 16384, [%2];"
                :: "r"(sdst), "l"(gsrc), "r"(mbn) : "memory");
        }

        // ---- LayerNorm stats: 4 threads per row (float4, aligned via X2S=68) ----
        {
            const int row = tid >> 2, q = tid & 3;
            const float* xr = x2 + row * X2S + q * 16;
            float s = 0.f, ss = 0.f;
#pragma unroll
            for (int j = 0; j < 4; ++j) {
                float4 v = *(const float4*)(xr + j * 4);
                s  += v.x + v.y + v.z + v.w;
                ss += v.x * v.x + v.y * v.y + v.z * v.z + v.w * v.w;
            }
            s  += __shfl_xor_sync(0xffffffffu, s, 1);
            ss += __shfl_xor_sync(0xffffffffu, ss, 1);
            s  += __shfl_xor_sync(0xffffffffu, s, 2);
            ss += __shfl_xor_sync(0xffffffffu, ss, 2);
            if (q == 0) {
                const float mu  = s * (1.f / 64.f);
                const float var = ss * (1.f / 64.f) - mu * mu;
                mu_s[row] = mu;
                rs_s[row] = rsqrtf(var + 1e-6f);
            }
        }
        __syncthreads();

        // ---- build normalized A fragments ----
        const int r0  = nloc * 16 + g;
        const float mu0 = mu_s[r0],     rs0 = rs_s[r0];
        const float mu1 = mu_s[r0 + 8], rs1 = rs_s[r0 + 8];
        unsigned A[4][4];
#pragma unroll
        for (int kt = 0; kt < 4; ++kt) {
            const int k0 = kt * 16 + 2 * tg;
            float2 sc0 = *(float2*)(lns_s + k0),     bi0 = *(float2*)(lnb_s + k0);
            float2 sc1 = *(float2*)(lns_s + k0 + 8), bi1 = *(float2*)(lnb_s + k0 + 8);
            float2 v;
            v = *(float2*)(x2 + r0 * X2S + k0);
            A[kt][0] = pk((v.x - mu0) * rs0 * sc0.x + bi0.x, (v.y - mu0) * rs0 * sc0.y + bi0.y);
            v = *(float2*)(x2 + (r0 + 8) * X2S + k0);
            A[kt][1] = pk((v.x - mu1) * rs1 * sc0.x + bi0.x, (v.y - mu1) * rs1 * sc0.y + bi0.y);
            v = *(float2*)(x2 + r0 * X2S + k0 + 8);
            A[kt][2] = pk((v.x - mu0) * rs0 * sc1.x + bi1.x, (v.y - mu0) * rs0 * sc1.y + bi1.y);
            v = *(float2*)(x2 + (r0 + 8) * X2S + k0 + 8);
            A[kt][3] = pk((v.x - mu1) * rs1 * sc1.x + bi1.x, (v.y - mu1) * rs1 * sc1.y + bi1.y);
        }

        // ---- MLP1: this warp's half (16 of 32 n-tiles) ----
        {
            float c1r[16][4];
#pragma unroll
            for (int nt = 0; nt < 16; ++nt) {
                const int col = (sub * 16 + nt) * 8 + 2 * tg;
                c1r[nt][0] = b1_s[col]; c1r[nt][1] = b1_s[col + 1];
                c1r[nt][2] = b1_s[col]; c1r[nt][3] = b1_s[col + 1];
            }
#pragma unroll
            for (int kt = 0; kt < 4; ++kt)
#pragma unroll
                for (int nt = 0; nt < 16; ++nt) {
                    const int ntg = sub * 16 + nt;
                    uint2 b = *(const uint2*)&w1p[((kt * 32 + ntg) * 32 + lane) * 2];
                    mma_bf16(c1r[nt], A[kt], b.x, b.y);
                }
#pragma unroll
            for (int nt = 0; nt < 16; ++nt) {
                const int ntg = sub * 16 + nt;
                const float p0 = fmaxf(c1r[nt][0], 0.f), p1 = fmaxf(c1r[nt][1], 0.f);
                const float p2 = fmaxf(c1r[nt][2], 0.f), p3 = fmaxf(c1r[nt][3], 0.f);
                h1[r0 * 132 + ntg * 4 + tg]       = pk(p0, p1);
                h1[(r0 + 8) * 132 + ntg * 4 + tg] = pk(p2, p3);
            }
        }
        // h1 is node-pair local: named barrier over the pair's 64 threads
        asm volatile("bar.sync %0, 64;" :: "r"(1 + nloc) : "memory");

        // ---- MLP2: this warp's quarter (4 of 8 n-tiles) ----
        float d[4][4];
#pragma unroll
        for (int nt = 0; nt < 4; ++nt) {
            const int col = (sub * 4 + nt) * 8 + 2 * tg;
            d[nt][0] = b2_s[col]; d[nt][1] = b2_s[col + 1];
            d[nt][2] = b2_s[col]; d[nt][3] = b2_s[col + 1];
        }
#pragma unroll
        for (int kt = 0; kt < 16; ++kt) {
            unsigned a[4];
            a[0] = h1[r0 * 132 + kt * 8 + tg];
            a[1] = h1[(r0 + 8) * 132 + kt * 8 + tg];
            a[2] = h1[r0 * 132 + kt * 8 + 4 + tg];
            a[3] = h1[(r0 + 8) * 132 + kt * 8 + 4 + tg];
#pragma unroll
            for (int nt = 0; nt < 4; ++nt) {
                uint2 b = *(const uint2*)&w2p[((kt * 8 + sub * 4 + nt) * 32 + lane) * 2];
                mma_bf16(d[nt], a, b.x, b.y);
            }
        }

        // ---- epilogue part 1: scaled d -> x2 smem (own rows only) ----
#pragma unroll
        for (int nt = 0; nt < 4; ++nt) {
            const int col = (sub * 4 + nt) * 8 + 2 * tg;
            const float l0 = ls_s[col], l1 = ls_s[col + 1];
            *(float2*)&x2[r0 * X2S + col] =
                make_float2(l0 * d[nt][0], l1 * d[nt][1]);
            *(float2*)&x2[(r0 + 8) * X2S + col] =
                make_float2(l0 * d[nt][2], l1 * d[nt][3]);
        }
        __syncthreads();   // all pairs done writing scaled outputs

        // ---- epilogue part 2: coalesced out = x2 + x (float4) ----
        {
            const float4* xr4 = (const float4*)(x + (size_t)nodebase * TILE);
            float4* o4 = (float4*)(out + (size_t)nodebase * TILE);
#pragma unroll
            for (int i = 0; i < 4; ++i) {
                const int j   = tid + i * 512;       // float4 index in 8-node tile
                const int row = j >> 4;              // 0..127 == x2 row
                const int col = (j & 15) * 4;
                float4 xv = xr4[j];
                const float* xp = &x2[row * X2S + col];
                o4[j] = make_float4(xp[0] + xv.x, xp[1] + xv.y,
                                    xp[2] + xv.z, xp[3] + xv.w);
            }
        }
        __syncthreads();   // protect x2/h1 for next group
    }
}

// =========================================================
extern "C" void kernel_launch(void* const* d_in, const int* in_sizes, int n_in,
                              void* d_out, int out_size)
{
    (void)in_sizes; (void)n_in; (void)out_size;
    const float* x   = (const float*)d_in[0];
    const float* kb  = (const float*)d_in[1];
    const float* fkb = (const float*)d_in[2];
    const int*   ei  = (const int*)  d_in[3];
    const float* kw  = (const float*)d_in[4];
    const float* fkw = (const float*)d_in[5];
    const float* cb  = (const float*)d_in[6];
    const float* lns = (const float*)d_in[7];
    const float* lnb = (const float*)d_in[8];
    const float* w1  = (const float*)d_in[9];
    const float* b1  = (const float*)d_in[10];
    const float* w2  = (const float*)d_in[11];
    const float* b2  = (const float*)d_in[12];
    const float* ls  = (const float*)d_in[13];
    float* out = (float*)d_out;

    const int edge_smem = 57344;   // 56KB: Wp 8K + KBS 16K + XB 32K
    cudaFuncSetAttribute(k_edge, cudaFuncAttributeMaxDynamicSharedMemorySize, edge_smem);
    cudaFuncSetAttribute(k_fuse, cudaFuncAttributeMaxDynamicSharedMemorySize, FUSE_SMEM_BYTES);

    k_prep0<<<2560, 256>>>(x);
    k_fk<<<OO * OO, 32>>>(fkb, fkw);
    k_pack<<<16, 256>>>(kw, w1, w2);
    k_edge<<<EE / 32, 256, edge_smem>>>(kb, ei);
    k_fuse<<<148, 512, FUSE_SMEM_BYTES>>>(x, cb, lns, lnb, b1, b2, ls, out);
}